// round 1
// baseline (speedup 1.0000x reference)
#include <cuda_runtime.h>
#include <math.h>

#define Nn  50000
#define Ein 800000
#define ET  850000      // Ein + Nn self loops
#define FIN 256
#define HID 64
#define H1  4

// ---------------- scratch (device globals; no allocation allowed) ----------
__device__ float g_xl1[Nn * FIN];
__device__ float g_xr1[Nn * FIN];
__device__ float g_e1[ET * H1];     // scores, later overwritten with exp(e-m)
__device__ float g_m1[Nn * H1];
__device__ float g_d1[Nn * H1];
__device__ float g_agg1[Nn * FIN];
__device__ float g_h[Nn * HID];
__device__ float g_xl2[Nn * HID];
__device__ float g_xr2[Nn * HID];
__device__ float g_e2[ET];
__device__ float g_m2[Nn];
__device__ float g_d2[Nn];
__device__ float g_agg2[Nn * HID];

// ---------------- helpers ----------------
__device__ __forceinline__ void atomicMaxF(float* addr, float v) {
    if (v >= 0.f) atomicMax((int*)addr, __float_as_int(v));
    else          atomicMin((unsigned int*)addr, __float_as_uint(v));
}

__device__ __forceinline__ void red4(float* p, float4 v) {
    asm volatile("red.global.add.v4.f32 [%0], {%1,%2,%3,%4};"
                 :: "l"(p), "f"(v.x), "f"(v.y), "f"(v.z), "f"(v.w) : "memory");
}

__device__ __forceinline__ float lrelu(float z) {
    return fmaxf(z, 0.f) + 0.2f * fminf(z, 0.f);
}

// ---------------- init ----------------
__global__ void k_init() {
    int i = blockIdx.x * blockDim.x + threadIdx.x;
    if (i < Nn * FIN) g_agg1[i] = 0.f;
    if (i < Nn * HID) g_agg2[i] = 0.f;
    if (i < Nn * H1)  { g_d1[i] = 0.f; g_m1[i] = -1e30f; }
    if (i < Nn)       { g_d2[i] = 0.f; g_m2[i] = -1e30f; }
}

// ---------------- tiled SGEMM: C[M,Nc] = A[M,K] @ B[K,Nc] ----------------
// BM=128, BN=64, BK=16, 256 threads (16x16), 8x4 per thread
__global__ void sgemm(const float* __restrict__ A, const float* __restrict__ B,
                      float* __restrict__ C, int M, int K, int Ncols) {
    const int BM = 128, BN = 64, BK = 16;
    __shared__ float As[BK][BM];
    __shared__ float Bs[BK][BN];
    int tx = threadIdx.x, ty = threadIdx.y;
    int tid = ty * 16 + tx;
    int m0 = blockIdx.y * BM, n0 = blockIdx.x * BN;

    float acc[8][4];
#pragma unroll
    for (int r = 0; r < 8; r++)
#pragma unroll
        for (int c = 0; c < 4; c++) acc[r][c] = 0.f;

    for (int k0 = 0; k0 < K; k0 += BK) {
        // A tile: 128x16 = 512 float4 loads (along K)
#pragma unroll
        for (int t = 0; t < 2; t++) {
            int i = tid + t * 256;          // 0..511
            int row = i >> 2, kq = i & 3;
            float4 v = make_float4(0.f, 0.f, 0.f, 0.f);
            int m = m0 + row;
            if (m < M) v = *(const float4*)(A + (size_t)m * K + k0 + kq * 4);
            As[kq * 4 + 0][row] = v.x;
            As[kq * 4 + 1][row] = v.y;
            As[kq * 4 + 2][row] = v.z;
            As[kq * 4 + 3][row] = v.w;
        }
        // B tile: 16x64 = 256 float4 loads
        {
            int k = tid >> 4, nq = tid & 15;
            float4 v = *(const float4*)(B + (size_t)(k0 + k) * Ncols + n0 + nq * 4);
            *(float4*)&Bs[k][nq * 4] = v;
        }
        __syncthreads();
#pragma unroll
        for (int kk = 0; kk < BK; kk++) {
            float4 a0 = *(float4*)&As[kk][ty * 8];
            float4 a1 = *(float4*)&As[kk][ty * 8 + 4];
            float4 b  = *(float4*)&Bs[kk][tx * 4];
            float ar[8] = {a0.x, a0.y, a0.z, a0.w, a1.x, a1.y, a1.z, a1.w};
            float br[4] = {b.x, b.y, b.z, b.w};
#pragma unroll
            for (int r = 0; r < 8; r++)
#pragma unroll
                for (int c = 0; c < 4; c++) acc[r][c] = fmaf(ar[r], br[c], acc[r][c]);
        }
        __syncthreads();
    }
#pragma unroll
    for (int r = 0; r < 8; r++) {
        int m = m0 + ty * 8 + r;
        if (m < M) {
            float4 o = make_float4(acc[r][0], acc[r][1], acc[r][2], acc[r][3]);
            *(float4*)(C + (size_t)m * Ncols + n0 + tx * 4) = o;
        }
    }
}

// ---------------- layer1 edge scores (warp per edge, H=4, C=64) ----------
__global__ void k_score1(const int* __restrict__ src, const int* __restrict__ dst,
                         const float* __restrict__ att) {
    int gid = blockIdx.x * blockDim.x + threadIdx.x;
    int e = gid >> 5, lane = gid & 31;
    if (e >= ET) return;
    int s, d;
    if (e < Ein) { s = src[e]; d = dst[e]; }
    else         { s = e - Ein; d = s; }
    const float4* xl = (const float4*)(g_xl1 + (size_t)s * FIN);
    const float4* xr = (const float4*)(g_xr1 + (size_t)d * FIN);
    const float4* at = (const float4*)att;
#pragma unroll
    for (int q = 0; q < 2; q++) {
        int j = lane + q * 32;              // float4 index 0..63; head = j/16
        float4 a = xl[j], b = xr[j], w = at[j];
        float p = 0.f, z;
        z = a.x + b.x; p = fmaf(lrelu(z), w.x, p);
        z = a.y + b.y; p = fmaf(lrelu(z), w.y, p);
        z = a.z + b.z; p = fmaf(lrelu(z), w.z, p);
        z = a.w + b.w; p = fmaf(lrelu(z), w.w, p);
        // reduce within 16-lane halves (each half = one head)
        p += __shfl_down_sync(0xffffffffu, p, 8, 16);
        p += __shfl_down_sync(0xffffffffu, p, 4, 16);
        p += __shfl_down_sync(0xffffffffu, p, 2, 16);
        p += __shfl_down_sync(0xffffffffu, p, 1, 16);
        if ((lane & 15) == 0) {
            int h = q * 2 + (lane >> 4);
            g_e1[(size_t)e * H1 + h] = p;
            atomicMaxF(&g_m1[d * H1 + h], p);
        }
    }
}

// ---------------- layer2 edge scores (warp per edge, H=1, C=64) ----------
__global__ void k_score2(const int* __restrict__ src, const int* __restrict__ dst,
                         const float* __restrict__ att) {
    int gid = blockIdx.x * blockDim.x + threadIdx.x;
    int e = gid >> 5, lane = gid & 31;
    if (e >= ET) return;
    int s, d;
    if (e < Ein) { s = src[e]; d = dst[e]; }
    else         { s = e - Ein; d = s; }
    float2 a = ((const float2*)(g_xl2 + (size_t)s * HID))[lane];
    float2 b = ((const float2*)(g_xr2 + (size_t)d * HID))[lane];
    float2 w = ((const float2*)att)[lane];
    float p = 0.f, z;
    z = a.x + b.x; p = fmaf(lrelu(z), w.x, p);
    z = a.y + b.y; p = fmaf(lrelu(z), w.y, p);
#pragma unroll
    for (int off = 16; off > 0; off >>= 1) p += __shfl_down_sync(0xffffffffu, p, off);
    if (lane == 0) {
        g_e2[e] = p;
        atomicMaxF(&g_m2[d], p);
    }
}

// ---------------- softmax exp + denom ----------------
__global__ void k_soft1(const int* __restrict__ dst) {
    int idx = blockIdx.x * blockDim.x + threadIdx.x;
    if (idx >= ET * H1) return;
    int e = idx >> 2, h = idx & 3;
    int d = (e < Ein) ? dst[e] : (e - Ein);
    float a = expf(g_e1[idx] - g_m1[d * H1 + h]);
    g_e1[idx] = a;
    atomicAdd(&g_d1[d * H1 + h], a);
}

__global__ void k_soft2(const int* __restrict__ dst) {
    int e = blockIdx.x * blockDim.x + threadIdx.x;
    if (e >= ET) return;
    int d = (e < Ein) ? dst[e] : (e - Ein);
    float a = expf(g_e2[e] - g_m2[d]);
    g_e2[e] = a;
    atomicAdd(&g_d2[d], a);
}

// ---------------- message scatter (vector atomics) ----------------
// layer1: thread per (edge, float4-chunk of 64); head = chunk/16
__global__ void k_scat1(const int* __restrict__ src, const int* __restrict__ dst) {
    int idx = blockIdx.x * blockDim.x + threadIdx.x;
    if (idx >= ET * 64) return;
    int e = idx >> 6, j = idx & 63, h = j >> 4;
    int s, d;
    if (e < Ein) { s = src[e]; d = dst[e]; }
    else         { s = e - Ein; d = s; }
    float alpha = g_e1[(size_t)e * H1 + h] / (g_d1[d * H1 + h] + 1e-16f);
    float4 v = ((const float4*)(g_xl1 + (size_t)s * FIN))[j];
    v.x *= alpha; v.y *= alpha; v.z *= alpha; v.w *= alpha;
    red4(&g_agg1[(size_t)d * FIN + j * 4], v);
}

// layer2: thread per (edge, float4-chunk of 16)
__global__ void k_scat2(const int* __restrict__ src, const int* __restrict__ dst) {
    int idx = blockIdx.x * blockDim.x + threadIdx.x;
    if (idx >= ET * 16) return;
    int e = idx >> 4, j = idx & 15;
    int s, d;
    if (e < Ein) { s = src[e]; d = dst[e]; }
    else         { s = e - Ein; d = s; }
    float alpha = g_e2[e] / (g_d2[d] + 1e-16f);
    float4 v = ((const float4*)(g_xl2 + (size_t)s * HID))[j];
    v.x *= alpha; v.y *= alpha; v.z *= alpha; v.w *= alpha;
    red4(&g_agg2[(size_t)d * HID + j * 4], v);
}

// ---------------- finalize: head-mean + bias + LN (+relu) ----------------
__global__ void k_final1(const float* __restrict__ bias, const float* __restrict__ lng,
                         const float* __restrict__ lnb) {
    int gid = blockIdx.x * blockDim.x + threadIdx.x;
    int n = gid >> 5, lane = gid & 31;
    if (n >= Nn) return;
    int c0 = lane, c1 = lane + 32;
    const float* base = g_agg1 + (size_t)n * FIN;
    float v0 = 0.25f * (base[c0] + base[64 + c0] + base[128 + c0] + base[192 + c0]) + bias[c0];
    float v1 = 0.25f * (base[c1] + base[64 + c1] + base[128 + c1] + base[192 + c1]) + bias[c1];
    float s = v0 + v1;
#pragma unroll
    for (int off = 16; off > 0; off >>= 1) s += __shfl_xor_sync(0xffffffffu, s, off);
    float mu = s * (1.f / 64.f);
    float d0 = v0 - mu, d1 = v1 - mu;
    float ss = d0 * d0 + d1 * d1;
#pragma unroll
    for (int off = 16; off > 0; off >>= 1) ss += __shfl_xor_sync(0xffffffffu, ss, off);
    float inv = rsqrtf(ss * (1.f / 64.f) + 1e-5f);
    g_h[(size_t)n * HID + c0] = fmaxf(d0 * inv * lng[c0] + lnb[c0], 0.f);
    g_h[(size_t)n * HID + c1] = fmaxf(d1 * inv * lng[c1] + lnb[c1], 0.f);
}

__global__ void k_final2(const float* __restrict__ bias, const float* __restrict__ lng,
                         const float* __restrict__ lnb, float* __restrict__ out) {
    int gid = blockIdx.x * blockDim.x + threadIdx.x;
    int n = gid >> 5, lane = gid & 31;
    if (n >= Nn) return;
    int c0 = lane, c1 = lane + 32;
    const float* base = g_agg2 + (size_t)n * HID;
    float v0 = base[c0] + bias[c0];
    float v1 = base[c1] + bias[c1];
    float s = v0 + v1;
#pragma unroll
    for (int off = 16; off > 0; off >>= 1) s += __shfl_xor_sync(0xffffffffu, s, off);
    float mu = s * (1.f / 64.f);
    float d0 = v0 - mu, d1 = v1 - mu;
    float ss = d0 * d0 + d1 * d1;
#pragma unroll
    for (int off = 16; off > 0; off >>= 1) ss += __shfl_xor_sync(0xffffffffu, ss, off);
    float inv = rsqrtf(ss * (1.f / 64.f) + 1e-5f);
    out[(size_t)n * HID + c0] = d0 * inv * lng[c0] + lnb[c0];
    out[(size_t)n * HID + c1] = d1 * inv * lng[c1] + lnb[c1];
}

// ---------------- launch ----------------
extern "C" void kernel_launch(void* const* d_in, const int* in_sizes, int n_in,
                              void* d_out, int out_size) {
    const float* x    = (const float*)d_in[0];
    const int*   ei   = (const int*)d_in[1];
    const float* W1l  = (const float*)d_in[2];
    const float* W1r  = (const float*)d_in[3];
    const float* att1 = (const float*)d_in[4];
    const float* b1   = (const float*)d_in[5];
    const float* ln1g = (const float*)d_in[6];
    const float* ln1b = (const float*)d_in[7];
    const float* W2l  = (const float*)d_in[8];
    const float* W2r  = (const float*)d_in[9];
    const float* att2 = (const float*)d_in[10];
    const float* b2   = (const float*)d_in[11];
    const float* ln2g = (const float*)d_in[12];
    const float* ln2b = (const float*)d_in[13];
    float* out = (float*)d_out;

    const int* srcp = ei;
    const int* dstp = ei + Ein;

    float *xl1p, *xr1p, *hp, *xl2p, *xr2p;
    cudaGetSymbolAddress((void**)&xl1p, g_xl1);
    cudaGetSymbolAddress((void**)&xr1p, g_xr1);
    cudaGetSymbolAddress((void**)&hp,   g_h);
    cudaGetSymbolAddress((void**)&xl2p, g_xl2);
    cudaGetSymbolAddress((void**)&xr2p, g_xr2);

    const int T = 256;

    // init scratch
    k_init<<<(Nn * FIN + T - 1) / T, T>>>();

    // layer1 GEMMs: [50000,256] @ [256,256]
    dim3 g1(FIN / 64, (Nn + 127) / 128), blk(16, 16);
    sgemm<<<g1, blk>>>(x, W1l, xl1p, Nn, FIN, FIN);
    sgemm<<<g1, blk>>>(x, W1r, xr1p, Nn, FIN, FIN);

    // layer1 attention
    k_score1<<<(ET * 32 + T - 1) / T, T>>>(srcp, dstp, att1);
    k_soft1<<<(ET * H1 + T - 1) / T, T>>>(dstp);
    k_scat1<<<(ET * 64 + T - 1) / T, T>>>(srcp, dstp);
    k_final1<<<(Nn * 32 + T - 1) / T, T>>>(b1, ln1g, ln1b);

    // layer2 GEMMs: [50000,64] @ [64,64]
    dim3 g2(1, (Nn + 127) / 128);
    sgemm<<<g2, blk>>>(hp, W2l, xl2p, Nn, HID, HID);
    sgemm<<<g2, blk>>>(hp, W2r, xr2p, Nn, HID, HID);

    // layer2 attention
    k_score2<<<(ET * 32 + T - 1) / T, T>>>(srcp, dstp, att2);
    k_soft2<<<(ET + T - 1) / T, T>>>(dstp);
    k_scat2<<<(ET * 16 + T - 1) / T, T>>>(srcp, dstp);
    k_final2<<<(Nn * 32 + T - 1) / T, T>>>(b2, ln2g, ln2b, out);
}

// round 2
// speedup vs baseline: 1.7098x; 1.7098x over previous
#include <cuda_runtime.h>
#include <math.h>

#define Nn  50000
#define Ein 800000
#define ET  850000      // Ein + Nn self loops
#define FIN 256
#define HID 64
#define H1  4

// ---------------- scratch (device globals; no allocation allowed) ----------
__device__ float g_xl1[Nn * FIN];
__device__ float g_xr1[Nn * FIN];
__device__ float g_h[Nn * HID];
__device__ float g_xl2[Nn * HID];
__device__ float g_xr2[Nn * HID];

__device__ int g_deg[Nn];
__device__ int g_cur[Nn];
__device__ int g_off[Nn + 1];
__device__ int g_csrc[ET];

__device__ __forceinline__ float lrelu(float z) {
    return fmaxf(z, 0.f) + 0.2f * fminf(z, 0.f);
}

// ---------------- CSR build ----------------
__global__ void k_zero() {
    int i = blockIdx.x * blockDim.x + threadIdx.x;
    if (i < Nn) { g_deg[i] = 0; g_cur[i] = 0; }
}

__global__ void k_hist(const int* __restrict__ dst) {
    int e = blockIdx.x * blockDim.x + threadIdx.x;
    if (e >= ET) return;
    int d = (e < Ein) ? dst[e] : (e - Ein);
    atomicAdd(&g_deg[d], 1);
}

__global__ void k_scan() {   // single block, 1024 threads
    __shared__ int wsum[32];
    __shared__ int carry_s;
    int t = threadIdx.x;
    if (t == 0) carry_s = 0;
    __syncthreads();
    for (int base = 0; base < Nn; base += 1024) {
        int i = base + t;
        int v = (i < Nn) ? g_deg[i] : 0;
        int x = v;
#pragma unroll
        for (int o = 1; o < 32; o <<= 1) {
            int y = __shfl_up_sync(0xffffffffu, x, o);
            if ((t & 31) >= o) x += y;
        }
        if ((t & 31) == 31) wsum[t >> 5] = x;
        __syncthreads();
        if (t < 32) {
            int wv = wsum[t];
#pragma unroll
            for (int o = 1; o < 32; o <<= 1) {
                int y = __shfl_up_sync(0xffffffffu, wv, o);
                if (t >= o) wv += y;
            }
            wsum[t] = wv;
        }
        __syncthreads();
        int excl = x - v + ((t >> 5) ? wsum[(t >> 5) - 1] : 0);
        int c = carry_s;
        if (i < Nn) g_off[i] = c + excl;
        int tot = wsum[31];
        __syncthreads();
        if (t == 0) carry_s = c + tot;
        __syncthreads();
    }
    if (t == 0) g_off[Nn] = carry_s;
}

__global__ void k_fill(const int* __restrict__ src, const int* __restrict__ dst) {
    int e = blockIdx.x * blockDim.x + threadIdx.x;
    if (e >= ET) return;
    int s, d;
    if (e < Ein) { s = src[e]; d = dst[e]; }
    else         { s = e - Ein; d = s; }
    int p = atomicAdd(&g_cur[d], 1);
    g_csrc[g_off[d] + p] = s;
}

// ---------------- tiled SGEMM: C[M,Nc] = A[M,K] @ B[K,Nc] ----------------
__global__ void sgemm(const float* __restrict__ A, const float* __restrict__ B,
                      float* __restrict__ C, int M, int K, int Ncols) {
    const int BM = 128, BN = 64, BK = 16;
    __shared__ float As[BK][BM];
    __shared__ float Bs[BK][BN];
    int tx = threadIdx.x, ty = threadIdx.y;
    int tid = ty * 16 + tx;
    int m0 = blockIdx.y * BM, n0 = blockIdx.x * BN;

    float acc[8][4];
#pragma unroll
    for (int r = 0; r < 8; r++)
#pragma unroll
        for (int c = 0; c < 4; c++) acc[r][c] = 0.f;

    for (int k0 = 0; k0 < K; k0 += BK) {
#pragma unroll
        for (int t = 0; t < 2; t++) {
            int i = tid + t * 256;
            int row = i >> 2, kq = i & 3;
            float4 v = make_float4(0.f, 0.f, 0.f, 0.f);
            int m = m0 + row;
            if (m < M) v = *(const float4*)(A + (size_t)m * K + k0 + kq * 4);
            As[kq * 4 + 0][row] = v.x;
            As[kq * 4 + 1][row] = v.y;
            As[kq * 4 + 2][row] = v.z;
            As[kq * 4 + 3][row] = v.w;
        }
        {
            int k = tid >> 4, nq = tid & 15;
            float4 v = *(const float4*)(B + (size_t)(k0 + k) * Ncols + n0 + nq * 4);
            *(float4*)&Bs[k][nq * 4] = v;
        }
        __syncthreads();
#pragma unroll
        for (int kk = 0; kk < BK; kk++) {
            float4 a0 = *(float4*)&As[kk][ty * 8];
            float4 a1 = *(float4*)&As[kk][ty * 8 + 4];
            float4 b  = *(float4*)&Bs[kk][tx * 4];
            float ar[8] = {a0.x, a0.y, a0.z, a0.w, a1.x, a1.y, a1.z, a1.w};
            float br[4] = {b.x, b.y, b.z, b.w};
#pragma unroll
            for (int r = 0; r < 8; r++)
#pragma unroll
                for (int c = 0; c < 4; c++) acc[r][c] = fmaf(ar[r], br[c], acc[r][c]);
        }
        __syncthreads();
    }
#pragma unroll
    for (int r = 0; r < 8; r++) {
        int m = m0 + ty * 8 + r;
        if (m < M) {
            float4 o = make_float4(acc[r][0], acc[r][1], acc[r][2], acc[r][3]);
            *(float4*)(C + (size_t)m * Ncols + n0 + tx * 4) = o;
        }
    }
}

// ---------------- layer1 fused: score + online softmax + aggregate + mean-heads
// ---------------- + bias + LN + relu.  One warp per dst node. ----------------
__global__ void k_gat1(const float* __restrict__ att, const float* __restrict__ bias,
                       const float* __restrict__ lng, const float* __restrict__ lnb) {
    int n = (blockIdx.x * blockDim.x + threadIdx.x) >> 5;
    int lane = threadIdx.x & 31;
    if (n >= Nn) return;

    const float4* xr = (const float4*)(g_xr1 + (size_t)n * FIN);
    float4 b0 = xr[lane], b1 = xr[lane + 32];
    const float4* at = (const float4*)att;
    float4 w0 = at[lane], w1 = at[lane + 32];

    int beg = g_off[n], end = g_off[n + 1];

    float m_a = -1e30f, m_b = -1e30f, den_a = 0.f, den_b = 0.f;
    float4 acc0 = make_float4(0.f, 0.f, 0.f, 0.f);
    float4 acc1 = make_float4(0.f, 0.f, 0.f, 0.f);

    int s = g_csrc[beg];
    const float4* xl = (const float4*)(g_xl1 + (size_t)s * FIN);
    float4 a0 = xl[lane], a1 = xl[lane + 32];

    for (int k = beg; k < end; k++) {
        float4 c0 = a0, c1 = a1;
        if (k + 1 < end) {
            int s2 = g_csrc[k + 1];
            const float4* xl2 = (const float4*)(g_xl1 + (size_t)s2 * FIN);
            a0 = xl2[lane]; a1 = xl2[lane + 32];
        }
        float p0 = 0.f, p1 = 0.f, z;
        z = c0.x + b0.x; p0 = fmaf(lrelu(z), w0.x, p0);
        z = c0.y + b0.y; p0 = fmaf(lrelu(z), w0.y, p0);
        z = c0.z + b0.z; p0 = fmaf(lrelu(z), w0.z, p0);
        z = c0.w + b0.w; p0 = fmaf(lrelu(z), w0.w, p0);
        z = c1.x + b1.x; p1 = fmaf(lrelu(z), w1.x, p1);
        z = c1.y + b1.y; p1 = fmaf(lrelu(z), w1.y, p1);
        z = c1.z + b1.z; p1 = fmaf(lrelu(z), w1.z, p1);
        z = c1.w + b1.w; p1 = fmaf(lrelu(z), w1.w, p1);
#pragma unroll
        for (int o = 8; o > 0; o >>= 1) {
            p0 += __shfl_xor_sync(0xffffffffu, p0, o, 16);
            p1 += __shfl_xor_sync(0xffffffffu, p1, o, 16);
        }
        // online softmax, group a (head lane>>4), group b (head 2+(lane>>4))
        float mn = fmaxf(m_a, p0);
        float sc = __expf(m_a - mn);
        float ww = __expf(p0 - mn);
        den_a = den_a * sc + ww;
        acc0.x = acc0.x * sc + ww * c0.x;
        acc0.y = acc0.y * sc + ww * c0.y;
        acc0.z = acc0.z * sc + ww * c0.z;
        acc0.w = acc0.w * sc + ww * c0.w;
        m_a = mn;

        mn = fmaxf(m_b, p1);
        sc = __expf(m_b - mn);
        ww = __expf(p1 - mn);
        den_b = den_b * sc + ww;
        acc1.x = acc1.x * sc + ww * c1.x;
        acc1.y = acc1.y * sc + ww * c1.y;
        acc1.z = acc1.z * sc + ww * c1.z;
        acc1.w = acc1.w * sc + ww * c1.w;
        m_b = mn;
    }

    float ra = 1.f / (den_a + 1e-16f);
    float rb = 1.f / (den_b + 1e-16f);
    // heads {h, h+2} for channel group q = lane&15
    float4 sum;
    sum.x = acc0.x * ra + acc1.x * rb;
    sum.y = acc0.y * ra + acc1.y * rb;
    sum.z = acc0.z * ra + acc1.z * rb;
    sum.w = acc0.w * ra + acc1.w * rb;
    // add partner half-warp (other 2 heads)
    sum.x += __shfl_xor_sync(0xffffffffu, sum.x, 16);
    sum.y += __shfl_xor_sync(0xffffffffu, sum.y, 16);
    sum.z += __shfl_xor_sync(0xffffffffu, sum.z, 16);
    sum.w += __shfl_xor_sync(0xffffffffu, sum.w, 16);

    int q = lane & 15;
    float4 bv = ((const float4*)bias)[q];
    float4 v;
    v.x = 0.25f * sum.x + bv.x;
    v.y = 0.25f * sum.y + bv.y;
    v.z = 0.25f * sum.z + bv.z;
    v.w = 0.25f * sum.w + bv.w;

    // LN over 64 channels (each value duplicated across half-warps -> /128)
    float ssum = v.x + v.y + v.z + v.w;
#pragma unroll
    for (int o = 16; o > 0; o >>= 1) ssum += __shfl_xor_sync(0xffffffffu, ssum, o);
    float mu = ssum * (1.f / 128.f);
    float dx = v.x - mu, dy = v.y - mu, dz = v.z - mu, dw = v.w - mu;
    float sq = dx * dx + dy * dy + dz * dz + dw * dw;
#pragma unroll
    for (int o = 16; o > 0; o >>= 1) sq += __shfl_xor_sync(0xffffffffu, sq, o);
    float inv = rsqrtf(sq * (1.f / 128.f) + 1e-5f);

    if (lane < 16) {
        float4 gv = ((const float4*)lng)[q];
        float4 b2 = ((const float4*)lnb)[q];
        float4 o;
        o.x = fmaxf(dx * inv * gv.x + b2.x, 0.f);
        o.y = fmaxf(dy * inv * gv.y + b2.y, 0.f);
        o.z = fmaxf(dz * inv * gv.z + b2.z, 0.f);
        o.w = fmaxf(dw * inv * gv.w + b2.w, 0.f);
        *(float4*)(g_h + (size_t)n * HID + 4 * q) = o;
    }
}

// ---------------- layer2 fused (H=1, C=64): warp per node ----------------
__global__ void k_gat2(const float* __restrict__ att, const float* __restrict__ bias,
                       const float* __restrict__ lng, const float* __restrict__ lnb,
                       float* __restrict__ out) {
    int n = (blockIdx.x * blockDim.x + threadIdx.x) >> 5;
    int lane = threadIdx.x & 31;
    if (n >= Nn) return;

    float2 b = ((const float2*)(g_xr2 + (size_t)n * HID))[lane];
    float2 w = ((const float2*)att)[lane];

    int beg = g_off[n], end = g_off[n + 1];
    float m = -1e30f, den = 0.f;
    float2 acc = make_float2(0.f, 0.f);

    int s = g_csrc[beg];
    float2 a = ((const float2*)(g_xl2 + (size_t)s * HID))[lane];

    for (int k = beg; k < end; k++) {
        float2 c = a;
        if (k + 1 < end) {
            int s2 = g_csrc[k + 1];
            a = ((const float2*)(g_xl2 + (size_t)s2 * HID))[lane];
        }
        float p = lrelu(c.x + b.x) * w.x + lrelu(c.y + b.y) * w.y;
#pragma unroll
        for (int o = 16; o > 0; o >>= 1) p += __shfl_xor_sync(0xffffffffu, p, o);
        float mn = fmaxf(m, p);
        float sc = __expf(m - mn);
        float ww = __expf(p - mn);
        den = den * sc + ww;
        acc.x = acc.x * sc + ww * c.x;
        acc.y = acc.y * sc + ww * c.y;
        m = mn;
    }

    float r = 1.f / (den + 1e-16f);
    float2 bv = ((const float2*)bias)[lane];
    float vx = acc.x * r + bv.x;
    float vy = acc.y * r + bv.y;

    float ssum = vx + vy;
#pragma unroll
    for (int o = 16; o > 0; o >>= 1) ssum += __shfl_xor_sync(0xffffffffu, ssum, o);
    float mu = ssum * (1.f / 64.f);
    float dx = vx - mu, dy = vy - mu;
    float sq = dx * dx + dy * dy;
#pragma unroll
    for (int o = 16; o > 0; o >>= 1) sq += __shfl_xor_sync(0xffffffffu, sq, o);
    float inv = rsqrtf(sq * (1.f / 64.f) + 1e-5f);

    float2 gv = ((const float2*)lng)[lane];
    float2 b2 = ((const float2*)lnb)[lane];
    float2 o;
    o.x = dx * inv * gv.x + b2.x;
    o.y = dy * inv * gv.y + b2.y;
    ((float2*)(out + (size_t)n * HID))[lane] = o;
}

// ---------------- launch ----------------
extern "C" void kernel_launch(void* const* d_in, const int* in_sizes, int n_in,
                              void* d_out, int out_size) {
    const float* x    = (const float*)d_in[0];
    const int*   ei   = (const int*)d_in[1];
    const float* W1l  = (const float*)d_in[2];
    const float* W1r  = (const float*)d_in[3];
    const float* att1 = (const float*)d_in[4];
    const float* b1   = (const float*)d_in[5];
    const float* ln1g = (const float*)d_in[6];
    const float* ln1b = (const float*)d_in[7];
    const float* W2l  = (const float*)d_in[8];
    const float* W2r  = (const float*)d_in[9];
    const float* att2 = (const float*)d_in[10];
    const float* b2   = (const float*)d_in[11];
    const float* ln2g = (const float*)d_in[12];
    const float* ln2b = (const float*)d_in[13];
    float* out = (float*)d_out;

    const int* srcp = ei;
    const int* dstp = ei + Ein;

    float *xl1p, *xr1p, *hp, *xl2p, *xr2p;
    cudaGetSymbolAddress((void**)&xl1p, g_xl1);
    cudaGetSymbolAddress((void**)&xr1p, g_xr1);
    cudaGetSymbolAddress((void**)&hp,   g_h);
    cudaGetSymbolAddress((void**)&xl2p, g_xl2);
    cudaGetSymbolAddress((void**)&xr2p, g_xr2);

    const int T = 256;

    // CSR build (shared by both layers)
    k_zero<<<(Nn + T - 1) / T, T>>>();
    k_hist<<<(ET + T - 1) / T, T>>>(dstp);
    k_scan<<<1, 1024>>>();
    k_fill<<<(ET + T - 1) / T, T>>>(srcp, dstp);

    // layer1 GEMMs: [50000,256] @ [256,256]
    dim3 g1(FIN / 64, (Nn + 127) / 128), blk(16, 16);
    sgemm<<<g1, blk>>>(x, W1l, xl1p, Nn, FIN, FIN);
    sgemm<<<g1, blk>>>(x, W1r, xr1p, Nn, FIN, FIN);

    // layer1 fused attention + LN + relu
    k_gat1<<<(Nn * 32 + T - 1) / T, T>>>(att1, b1, ln1g, ln1b);

    // layer2 GEMMs: [50000,64] @ [64,64]
    dim3 g2(1, (Nn + 127) / 128);
    sgemm<<<g2, blk>>>(hp, W2l, xl2p, Nn, HID, HID);
    sgemm<<<g2, blk>>>(hp, W2r, xr2p, Nn, HID, HID);

    // layer2 fused attention + LN -> out
    k_gat2<<<(Nn * 32 + T - 1) / T, T>>>(att2, b2, ln2g, ln2b, out);
}

// round 8
// speedup vs baseline: 2.3670x; 1.3843x over previous
#include <cuda_runtime.h>
#include <cuda_bf16.h>
#include <math.h>
#include <stdint.h>

#define Nn  50000
#define Ein 800000
#define ET  850000      // Ein + Nn self loops
#define FIN 256
#define HID 64
#define H1  4
#define NT  512         // xl (256) ++ xr (256)

// ---------------- scratch (device globals; no allocation allowed) ----------
__device__ float g_xlr[(size_t)Nn * NT];    // layer1 projections [xl | xr]
__device__ __align__(16) __nv_bfloat16 g_xhi[Nn * FIN];
__device__ __align__(16) __nv_bfloat16 g_xlo[Nn * FIN];
__device__ __align__(16) __nv_bfloat16 g_whi[NT * FIN];   // Wt[n][k]
__device__ __align__(16) __nv_bfloat16 g_wlo[NT * FIN];
__device__ float g_h[Nn * HID];
__device__ float g_xl2[Nn * HID];
__device__ float g_xr2[Nn * HID];

__device__ int g_deg[Nn];
__device__ int g_cur[Nn];
__device__ int g_off[Nn + 1];
__device__ int g_csrc[ET];

__device__ __forceinline__ float lrelu(float z) {
    return fmaxf(z, 0.f) + 0.2f * fminf(z, 0.f);
}

// ---------------- CSR build ----------------
__global__ void k_zero() {
    int i = blockIdx.x * blockDim.x + threadIdx.x;
    if (i < Nn) { g_deg[i] = 0; g_cur[i] = 0; }
}

__global__ void k_hist(const int* __restrict__ dst) {
    int e = blockIdx.x * blockDim.x + threadIdx.x;
    if (e >= ET) return;
    int d = (e < Ein) ? dst[e] : (e - Ein);
    atomicAdd(&g_deg[d], 1);
}

__global__ void k_scan() {   // single block, 1024 threads
    __shared__ int wsum[32];
    __shared__ int carry_s;
    int t = threadIdx.x;
    if (t == 0) carry_s = 0;
    __syncthreads();
    for (int base = 0; base < Nn; base += 1024) {
        int i = base + t;
        int v = (i < Nn) ? g_deg[i] : 0;
        int x = v;
#pragma unroll
        for (int o = 1; o < 32; o <<= 1) {
            int y = __shfl_up_sync(0xffffffffu, x, o);
            if ((t & 31) >= o) x += y;
        }
        if ((t & 31) == 31) wsum[t >> 5] = x;
        __syncthreads();
        if (t < 32) {
            int wv = wsum[t];
#pragma unroll
            for (int o = 1; o < 32; o <<= 1) {
                int y = __shfl_up_sync(0xffffffffu, wv, o);
                if (t >= o) wv += y;
            }
            wsum[t] = wv;
        }
        __syncthreads();
        int excl = x - v + ((t >> 5) ? wsum[(t >> 5) - 1] : 0);
        int c = carry_s;
        if (i < Nn) g_off[i] = c + excl;
        int tot = wsum[31];
        __syncthreads();
        if (t == 0) carry_s = c + tot;
        __syncthreads();
    }
    if (t == 0) g_off[Nn] = carry_s;
}

__global__ void k_fill(const int* __restrict__ src, const int* __restrict__ dst) {
    int e = blockIdx.x * blockDim.x + threadIdx.x;
    if (e >= ET) return;
    int s, d;
    if (e < Ein) { s = src[e]; d = dst[e]; }
    else         { s = e - Ein; d = s; }
    int p = atomicAdd(&g_cur[d], 1);
    g_csrc[g_off[d] + p] = s;
}

// ---------------- fp32 -> bf16 hi/lo split ----------------
__global__ void k_convx(const float* __restrict__ x) {
    int i = blockIdx.x * blockDim.x + threadIdx.x;
    if (i >= Nn * FIN) return;
    float v = x[i];
    __nv_bfloat16 hi = __float2bfloat16(v);
    g_xhi[i] = hi;
    g_xlo[i] = __float2bfloat16(v - __bfloat162float(hi));
}

__global__ void k_convw(const float* __restrict__ Wl, const float* __restrict__ Wr) {
    int i = blockIdx.x * blockDim.x + threadIdx.x;
    if (i >= NT * FIN) return;
    int n = i >> 8, k = i & 255;   // FIN = 256
    float v = (n < 256) ? Wl[k * 256 + n] : Wr[k * 256 + (n - 256)];
    __nv_bfloat16 hi = __float2bfloat16(v);
    g_whi[i] = hi;
    g_wlo[i] = __float2bfloat16(v - __bfloat162float(hi));
}

// ---------------- layer1 GEMM via mma.sync bf16-split ----------------
// C[50000, 512] = X[50000, 256] @ Wt^T.  CTA tile 128x128, 8 warps of 32x64.
// smem tiles 128 x 64 bf16, row stride 72 (conflict-free fragment loads).
#define TS 72
#define SM_AH 0
#define SM_AL (128 * TS)
#define SM_BH (2 * 128 * TS)
#define SM_BL (3 * 128 * TS)
#define SM_ELEMS (4 * 128 * TS)

__device__ __forceinline__ void mma16816(float* c, const uint32_t* a, uint32_t b0, uint32_t b1) {
    asm volatile(
        "mma.sync.aligned.m16n8k16.row.col.f32.bf16.bf16.f32 "
        "{%0,%1,%2,%3}, {%4,%5,%6,%7}, {%8,%9}, {%0,%1,%2,%3};"
        : "+f"(c[0]), "+f"(c[1]), "+f"(c[2]), "+f"(c[3])
        : "r"(a[0]), "r"(a[1]), "r"(a[2]), "r"(a[3]), "r"(b0), "r"(b1));
}

__global__ void __launch_bounds__(256, 2) k_gemm1() {
    extern __shared__ __nv_bfloat16 sm[];
    int tid = threadIdx.x;
    int wid = tid >> 5, lane = tid & 31;
    int m0 = blockIdx.y * 128, n0 = blockIdx.x * 128;
    int wm = (wid & 3) * 32, wn = (wid >> 2) * 64;
    int gr = lane >> 2, gc2 = (lane & 3) * 2;

    float acc[2][8][4];
#pragma unroll
    for (int mi = 0; mi < 2; mi++)
#pragma unroll
        for (int f = 0; f < 8; f++)
#pragma unroll
            for (int j = 0; j < 4; j++) acc[mi][f][j] = 0.f;

    for (int kc = 0; kc < 4; kc++) {
        int k0 = kc * 64;
        // A tiles (hi+lo): 128 rows x 64 cols
#pragma unroll
        for (int u = tid; u < 1024; u += 256) {
            int r = u >> 3, i = u & 7;
            int m = m0 + r;
            uint4 vh = make_uint4(0u, 0u, 0u, 0u), vl = vh;
            if (m < Nn) {
                vh = ((const uint4*)(g_xhi + (size_t)m * FIN + k0))[i];
                vl = ((const uint4*)(g_xlo + (size_t)m * FIN + k0))[i];
            }
            *(uint4*)(sm + SM_AH + r * TS + i * 8) = vh;
            *(uint4*)(sm + SM_AL + r * TS + i * 8) = vl;
        }
        // B tiles (hi+lo): 128 n-rows x 64 cols
#pragma unroll
        for (int u = tid; u < 1024; u += 256) {
            int r = u >> 3, i = u & 7;
            int n = n0 + r;
            uint4 vh = ((const uint4*)(g_whi + (size_t)n * FIN + k0))[i];
            uint4 vl = ((const uint4*)(g_wlo + (size_t)n * FIN + k0))[i];
            *(uint4*)(sm + SM_BH + r * TS + i * 8) = vh;
            *(uint4*)(sm + SM_BL + r * TS + i * 8) = vl;
        }
        __syncthreads();

#pragma unroll
        for (int kk = 0; kk < 64; kk += 16) {
            uint32_t ah[2][4], al[2][4];
#pragma unroll
            for (int mi = 0; mi < 2; mi++) {
                int r0 = wm + mi * 16 + gr;
                ah[mi][0] = *(const uint32_t*)(sm + SM_AH + (r0)     * TS + kk + gc2);
                ah[mi][1] = *(const uint32_t*)(sm + SM_AH + (r0 + 8) * TS + kk + gc2);
                ah[mi][2] = *(const uint32_t*)(sm + SM_AH + (r0)     * TS + kk + gc2 + 8);
                ah[mi][3] = *(const uint32_t*)(sm + SM_AH + (r0 + 8) * TS + kk + gc2 + 8);
                al[mi][0] = *(const uint32_t*)(sm + SM_AL + (r0)     * TS + kk + gc2);
                al[mi][1] = *(const uint32_t*)(sm + SM_AL + (r0 + 8) * TS + kk + gc2);
                al[mi][2] = *(const uint32_t*)(sm + SM_AL + (r0)     * TS + kk + gc2 + 8);
                al[mi][3] = *(const uint32_t*)(sm + SM_AL + (r0 + 8) * TS + kk + gc2 + 8);
            }
#pragma unroll
            for (int f = 0; f < 8; f++) {
                int nb = wn + f * 8 + gr;
                uint32_t bh0 = *(const uint32_t*)(sm + SM_BH + nb * TS + kk + gc2);
                uint32_t bh1 = *(const uint32_t*)(sm + SM_BH + nb * TS + kk + gc2 + 8);
                uint32_t bl0 = *(const uint32_t*)(sm + SM_BL + nb * TS + kk + gc2);
                uint32_t bl1 = *(const uint32_t*)(sm + SM_BL + nb * TS + kk + gc2 + 8);
#pragma unroll
                for (int mi = 0; mi < 2; mi++) {
                    mma16816(acc[mi][f], ah[mi], bh0, bh1);
                    mma16816(acc[mi][f], ah[mi], bl0, bl1);
                    mma16816(acc[mi][f], al[mi], bh0, bh1);
                }
            }
        }
        __syncthreads();
    }

    // epilogue
#pragma unroll
    for (int mi = 0; mi < 2; mi++) {
        int r0 = m0 + wm + mi * 16 + gr;
#pragma unroll
        for (int f = 0; f < 8; f++) {
            int col = n0 + wn + f * 8 + gc2;
            if (r0 < Nn)
                *(float2*)(g_xlr + (size_t)r0 * NT + col) = make_float2(acc[mi][f][0], acc[mi][f][1]);
            if (r0 + 8 < Nn)
                *(float2*)(g_xlr + (size_t)(r0 + 8) * NT + col) = make_float2(acc[mi][f][2], acc[mi][f][3]);
        }
    }
}

// ---------------- fp32 tiled SGEMM (layer 2 only) ----------------
__global__ void sgemm(const float* __restrict__ A, const float* __restrict__ B,
                      float* __restrict__ C, int M, int K, int Ncols) {
    const int BM = 128, BK = 16;
    __shared__ float As[BK][BM];
    __shared__ float Bs[BK][64];
    int tx = threadIdx.x, ty = threadIdx.y;
    int tid = ty * 16 + tx;
    int m0 = blockIdx.y * BM, n0 = blockIdx.x * 64;

    float acc[8][4];
#pragma unroll
    for (int r = 0; r < 8; r++)
#pragma unroll
        for (int c = 0; c < 4; c++) acc[r][c] = 0.f;

    for (int k0 = 0; k0 < K; k0 += BK) {
#pragma unroll
        for (int t = 0; t < 2; t++) {
            int i = tid + t * 256;
            int row = i >> 2, kq = i & 3;
            float4 v = make_float4(0.f, 0.f, 0.f, 0.f);
            int m = m0 + row;
            if (m < M) v = *(const float4*)(A + (size_t)m * K + k0 + kq * 4);
            As[kq * 4 + 0][row] = v.x;
            As[kq * 4 + 1][row] = v.y;
            As[kq * 4 + 2][row] = v.z;
            As[kq * 4 + 3][row] = v.w;
        }
        {
            int k = tid >> 4, nq = tid & 15;
            float4 v = *(const float4*)(B + (size_t)(k0 + k) * Ncols + n0 + nq * 4);
            *(float4*)&Bs[k][nq * 4] = v;
        }
        __syncthreads();
#pragma unroll
        for (int kk = 0; kk < BK; kk++) {
            float4 a0 = *(float4*)&As[kk][ty * 8];
            float4 a1 = *(float4*)&As[kk][ty * 8 + 4];
            float4 b  = *(float4*)&Bs[kk][tx * 4];
            float ar[8] = {a0.x, a0.y, a0.z, a0.w, a1.x, a1.y, a1.z, a1.w};
            float br[4] = {b.x, b.y, b.z, b.w};
#pragma unroll
            for (int r = 0; r < 8; r++)
#pragma unroll
                for (int c = 0; c < 4; c++) acc[r][c] = fmaf(ar[r], br[c], acc[r][c]);
        }
        __syncthreads();
    }
#pragma unroll
    for (int r = 0; r < 8; r++) {
        int m = m0 + ty * 8 + r;
        if (m < M) {
            float4 o = make_float4(acc[r][0], acc[r][1], acc[r][2], acc[r][3]);
            *(float4*)(C + (size_t)m * Ncols + n0 + tx * 4) = o;
        }
    }
}

// ---------------- layer1 fused attention + LN + relu (warp per node) ------
__global__ void k_gat1(const float* __restrict__ att, const float* __restrict__ bias,
                       const float* __restrict__ lng, const float* __restrict__ lnb) {
    int n = (blockIdx.x * blockDim.x + threadIdx.x) >> 5;
    int lane = threadIdx.x & 31;
    if (n >= Nn) return;

    const float4* xr = (const float4*)(g_xlr + (size_t)n * NT + 256);
    float4 b0 = xr[lane], b1 = xr[lane + 32];
    const float4* at = (const float4*)att;
    float4 w0 = at[lane], w1 = at[lane + 32];

    int beg = g_off[n], end = g_off[n + 1];

    float m_a = -1e30f, m_b = -1e30f, den_a = 0.f, den_b = 0.f;
    float4 acc0 = make_float4(0.f, 0.f, 0.f, 0.f);
    float4 acc1 = make_float4(0.f, 0.f, 0.f, 0.f);

    int s = g_csrc[beg];
    const float4* xl = (const float4*)(g_xlr + (size_t)s * NT);
    float4 a0 = xl[lane], a1 = xl[lane + 32];

    for (int k = beg; k < end; k++) {
        float4 c0 = a0, c1 = a1;
        if (k + 1 < end) {
            int s2 = g_csrc[k + 1];
            const float4* xl2 = (const float4*)(g_xlr + (size_t)s2 * NT);
            a0 = xl2[lane]; a1 = xl2[lane + 32];
        }
        float p0 = 0.f, p1 = 0.f, z;
        z = c0.x + b0.x; p0 = fmaf(lrelu(z), w0.x, p0);
        z = c0.y + b0.y; p0 = fmaf(lrelu(z), w0.y, p0);
        z = c0.z + b0.z; p0 = fmaf(lrelu(z), w0.z, p0);
        z = c0.w + b0.w; p0 = fmaf(lrelu(z), w0.w, p0);
        z = c1.x + b1.x; p1 = fmaf(lrelu(z), w1.x, p1);
        z = c1.y + b1.y; p1 = fmaf(lrelu(z), w1.y, p1);
        z = c1.z + b1.z; p1 = fmaf(lrelu(z), w1.z, p1);
        z = c1.w + b1.w; p1 = fmaf(lrelu(z), w1.w, p1);
#pragma unroll
        for (int o = 8; o > 0; o >>= 1) {
            p0 += __shfl_xor_sync(0xffffffffu, p0, o, 16);
            p1 += __shfl_xor_sync(0xffffffffu, p1, o, 16);
        }
        float mn = fmaxf(m_a, p0);
        float sc = __expf(m_a - mn);
        float ww = __expf(p0 - mn);
        den_a = den_a * sc + ww;
        acc0.x = acc0.x * sc + ww * c0.x;
        acc0.y = acc0.y * sc + ww * c0.y;
        acc0.z = acc0.z * sc + ww * c0.z;
        acc0.w = acc0.w * sc + ww * c0.w;
        m_a = mn;

        mn = fmaxf(m_b, p1);
        sc = __expf(m_b - mn);
        ww = __expf(p1 - mn);
        den_b = den_b * sc + ww;
        acc1.x = acc1.x * sc + ww * c1.x;
        acc1.y = acc1.y * sc + ww * c1.y;
        acc1.z = acc1.z * sc + ww * c1.z;
        acc1.w = acc1.w * sc + ww * c1.w;
        m_b = mn;
    }

    float ra = 1.f / (den_a + 1e-16f);
    float rb = 1.f / (den_b + 1e-16f);
    float4 sum;
    sum.x = acc0.x * ra + acc1.x * rb;
    sum.y = acc0.y * ra + acc1.y * rb;
    sum.z = acc0.z * ra + acc1.z * rb;
    sum.w = acc0.w * ra + acc1.w * rb;
    sum.x += __shfl_xor_sync(0xffffffffu, sum.x, 16);
    sum.y += __shfl_xor_sync(0xffffffffu, sum.y, 16);
    sum.z += __shfl_xor_sync(0xffffffffu, sum.z, 16);
    sum.w += __shfl_xor_sync(0xffffffffu, sum.w, 16);

    int q = lane & 15;
    float4 bv = ((const float4*)bias)[q];
    float4 v;
    v.x = 0.25f * sum.x + bv.x;
    v.y = 0.25f * sum.y + bv.y;
    v.z = 0.25f * sum.z + bv.z;
    v.w = 0.25f * sum.w + bv.w;

    float ssum = v.x + v.y + v.z + v.w;
#pragma unroll
    for (int o = 16; o > 0; o >>= 1) ssum += __shfl_xor_sync(0xffffffffu, ssum, o);
    float mu = ssum * (1.f / 128.f);
    float dx = v.x - mu, dy = v.y - mu, dz = v.z - mu, dw = v.w - mu;
    float sq = dx * dx + dy * dy + dz * dz + dw * dw;
#pragma unroll
    for (int o = 16; o > 0; o >>= 1) sq += __shfl_xor_sync(0xffffffffu, sq, o);
    float inv = rsqrtf(sq * (1.f / 128.f) + 1e-5f);

    if (lane < 16) {
        float4 gv = ((const float4*)lng)[q];
        float4 b2 = ((const float4*)lnb)[q];
        float4 o;
        o.x = fmaxf(dx * inv * gv.x + b2.x, 0.f);
        o.y = fmaxf(dy * inv * gv.y + b2.y, 0.f);
        o.z = fmaxf(dz * inv * gv.z + b2.z, 0.f);
        o.w = fmaxf(dw * inv * gv.w + b2.w, 0.f);
        *(float4*)(g_h + (size_t)n * HID + 4 * q) = o;
    }
}

// ---------------- layer2 fused (H=1, C=64): warp per node ----------------
__global__ void k_gat2(const float* __restrict__ att, const float* __restrict__ bias,
                       const float* __restrict__ lng, const float* __restrict__ lnb,
                       float* __restrict__ out) {
    int n = (blockIdx.x * blockDim.x + threadIdx.x) >> 5;
    int lane = threadIdx.x & 31;
    if (n >= Nn) return;

    float2 b = ((const float2*)(g_xr2 + (size_t)n * HID))[lane];
    float2 w = ((const float2*)att)[lane];

    int beg = g_off[n], end = g_off[n + 1];
    float m = -1e30f, den = 0.f;
    float2 acc = make_float2(0.f, 0.f);

    int s = g_csrc[beg];
    float2 a = ((const float2*)(g_xl2 + (size_t)s * HID))[lane];

    for (int k = beg; k < end; k++) {
        float2 c = a;
        if (k + 1 < end) {
            int s2 = g_csrc[k + 1];
            a = ((const float2*)(g_xl2 + (size_t)s2 * HID))[lane];
        }
        float p = lrelu(c.x + b.x) * w.x + lrelu(c.y + b.y) * w.y;
#pragma unroll
        for (int o = 16; o > 0; o >>= 1) p += __shfl_xor_sync(0xffffffffu, p, o);
        float mn = fmaxf(m, p);
        float sc = __expf(m - mn);
        float ww = __expf(p - mn);
        den = den * sc + ww;
        acc.x = acc.x * sc + ww * c.x;
        acc.y = acc.y * sc + ww * c.y;
        m = mn;
    }

    float r = 1.f / (den + 1e-16f);
    float2 bv = ((const float2*)bias)[lane];
    float vx = acc.x * r + bv.x;
    float vy = acc.y * r + bv.y;

    float ssum = vx + vy;
#pragma unroll
    for (int o = 16; o > 0; o >>= 1) ssum += __shfl_xor_sync(0xffffffffu, ssum, o);
    float mu = ssum * (1.f / 64.f);
    float dx = vx - mu, dy = vy - mu;
    float sq = dx * dx + dy * dy;
#pragma unroll
    for (int o = 16; o > 0; o >>= 1) sq += __shfl_xor_sync(0xffffffffu, sq, o);
    float inv = rsqrtf(sq * (1.f / 64.f) + 1e-5f);

    float2 gv = ((const float2*)lng)[lane];
    float2 b2 = ((const float2*)lnb)[lane];
    float2 o;
    o.x = dx * inv * gv.x + b2.x;
    o.y = dy * inv * gv.y + b2.y;
    ((float2*)(out + (size_t)n * HID))[lane] = o;
}

// ---------------- launch ----------------
extern "C" void kernel_launch(void* const* d_in, const int* in_sizes, int n_in,
                              void* d_out, int out_size) {
    const float* x    = (const float*)d_in[0];
    const int*   ei   = (const int*)d_in[1];
    const float* W1l  = (const float*)d_in[2];
    const float* W1r  = (const float*)d_in[3];
    const float* att1 = (const float*)d_in[4];
    const float* b1   = (const float*)d_in[5];
    const float* ln1g = (const float*)d_in[6];
    const float* ln1b = (const float*)d_in[7];
    const float* W2l  = (const float*)d_in[8];
    const float* W2r  = (const float*)d_in[9];
    const float* att2 = (const float*)d_in[10];
    const float* b2   = (const float*)d_in[11];
    const float* ln2g = (const float*)d_in[12];
    const float* ln2b = (const float*)d_in[13];
    float* out = (float*)d_out;

    const int* srcp = ei;
    const int* dstp = ei + Ein;

    float *hp, *xl2p, *xr2p;
    cudaGetSymbolAddress((void**)&hp,   g_h);
    cudaGetSymbolAddress((void**)&xl2p, g_xl2);
    cudaGetSymbolAddress((void**)&xr2p, g_xr2);

    const int T = 256;

    // CSR build (shared by both layers)
    k_zero<<<(Nn + T - 1) / T, T>>>();
    k_hist<<<(ET + T - 1) / T, T>>>(dstp);
    k_scan<<<1, 1024>>>();
    k_fill<<<(ET + T - 1) / T, T>>>(srcp, dstp);

    // bf16 hi/lo conversions
    k_convw<<<(NT * FIN + T - 1) / T, T>>>(W1l, W1r);
    k_convx<<<(Nn * FIN + T - 1) / T, T>>>(x);

    // layer1 GEMM on tensor cores via mma.sync (bf16-split, xl|xr fused, N=512)
    size_t smbytes = SM_ELEMS * sizeof(__nv_bfloat16);   // 73728
    cudaFuncSetAttribute(k_gemm1, cudaFuncAttributeMaxDynamicSharedMemorySize, (int)smbytes);
    dim3 gg(NT / 128, (Nn + 127) / 128);
    k_gemm1<<<gg, 256, smbytes>>>();

    // layer1 fused attention + LN + relu
    k_gat1<<<(Nn * 32 + T - 1) / T, T>>>(att1, b1, ln1g, ln1b);

    // layer2 GEMMs: [50000,64] @ [64,64] (fp32, tiny)
    dim3 g2(1, (Nn + 127) / 128), blk(16, 16);
    sgemm<<<g2, blk>>>(hp, W2l, xl2p, Nn, HID, HID);
    sgemm<<<g2, blk>>>(hp, W2r, xr2p, Nn, HID, HID);

    // layer2 fused attention + LN -> out
    k_gat2<<<(Nn * 32 + T - 1) / T, T>>>(att2, b2, ln2g, ln2b, out);
}

// round 9
// speedup vs baseline: 2.4749x; 1.0456x over previous
#include <cuda_runtime.h>
#include <cuda_bf16.h>
#include <math.h>
#include <stdint.h>

#define Nn  50000
#define Ein 800000
#define ET  850000      // Ein + Nn self loops
#define FIN 256
#define HID 64
#define H1  4
#define NT  512         // xl (256) ++ xr (256)

// ---------------- scratch (device globals; no allocation allowed) ----------
__device__ float g_xlr[(size_t)Nn * NT];    // layer1 projections [xl | xr]
__device__ __align__(16) __nv_bfloat16 g_xhi[Nn * FIN];
__device__ __align__(16) __nv_bfloat16 g_xlo[Nn * FIN];
__device__ __align__(16) __nv_bfloat16 g_whi[NT * FIN];   // Wt[n][k]
__device__ __align__(16) __nv_bfloat16 g_wlo[NT * FIN];
__device__ float g_h[Nn * HID];
__device__ float g_w2[64 * 128];            // packed [W2l | W2r], B[k][n]
__device__ float g_xlr2[(size_t)Nn * 128];  // layer2 projections [xl2 | xr2]

__device__ int g_deg[Nn];
__device__ int g_cur[Nn];
__device__ int g_off[Nn + 1];
__device__ int g_csrc[ET];

__device__ __forceinline__ float lrelu(float z) {
    return fmaxf(z, 0.f) + 0.2f * fminf(z, 0.f);
}

// ---------------- CSR build ----------------
__global__ void k_zero() {
    int i = blockIdx.x * blockDim.x + threadIdx.x;
    if (i < Nn) { g_deg[i] = 0; g_cur[i] = 0; }
}

__global__ void k_hist(const int* __restrict__ dst) {
    int e = blockIdx.x * blockDim.x + threadIdx.x;
    if (e >= ET) return;
    int d = (e < Ein) ? dst[e] : (e - Ein);
    atomicAdd(&g_deg[d], 1);
}

__global__ void k_scan() {   // single block, 1024 threads
    __shared__ int wsum[32];
    __shared__ int carry_s;
    int t = threadIdx.x;
    if (t == 0) carry_s = 0;
    __syncthreads();
    for (int base = 0; base < Nn; base += 1024) {
        int i = base + t;
        int v = (i < Nn) ? g_deg[i] : 0;
        int x = v;
#pragma unroll
        for (int o = 1; o < 32; o <<= 1) {
            int y = __shfl_up_sync(0xffffffffu, x, o);
            if ((t & 31) >= o) x += y;
        }
        if ((t & 31) == 31) wsum[t >> 5] = x;
        __syncthreads();
        if (t < 32) {
            int wv = wsum[t];
#pragma unroll
            for (int o = 1; o < 32; o <<= 1) {
                int y = __shfl_up_sync(0xffffffffu, wv, o);
                if (t >= o) wv += y;
            }
            wsum[t] = wv;
        }
        __syncthreads();
        int excl = x - v + ((t >> 5) ? wsum[(t >> 5) - 1] : 0);
        int c = carry_s;
        if (i < Nn) g_off[i] = c + excl;
        int tot = wsum[31];
        __syncthreads();
        if (t == 0) carry_s = c + tot;
        __syncthreads();
    }
    if (t == 0) g_off[Nn] = carry_s;
}

__global__ void k_fill(const int* __restrict__ src, const int* __restrict__ dst) {
    int e = blockIdx.x * blockDim.x + threadIdx.x;
    if (e >= ET) return;
    int s, d;
    if (e < Ein) { s = src[e]; d = dst[e]; }
    else         { s = e - Ein; d = s; }
    int p = atomicAdd(&g_cur[d], 1);
    g_csrc[g_off[d] + p] = s;
}

// ---------------- fp32 -> bf16 hi/lo split ----------------
__global__ void k_convx(const float* __restrict__ x) {
    int i = blockIdx.x * blockDim.x + threadIdx.x;
    if (i >= Nn * FIN) return;
    float v = x[i];
    __nv_bfloat16 hi = __float2bfloat16(v);
    g_xhi[i] = hi;
    g_xlo[i] = __float2bfloat16(v - __bfloat162float(hi));
}

__global__ void k_convw(const float* __restrict__ Wl, const float* __restrict__ Wr) {
    int i = blockIdx.x * blockDim.x + threadIdx.x;
    if (i >= NT * FIN) return;
    int n = i >> 8, k = i & 255;   // FIN = 256
    float v = (n < 256) ? Wl[k * 256 + n] : Wr[k * 256 + (n - 256)];
    __nv_bfloat16 hi = __float2bfloat16(v);
    g_whi[i] = hi;
    g_wlo[i] = __float2bfloat16(v - __bfloat162float(hi));
}

__global__ void k_packw2(const float* __restrict__ Wl, const float* __restrict__ Wr) {
    int i = blockIdx.x * blockDim.x + threadIdx.x;
    if (i >= 64 * 128) return;
    int k = i >> 7, n = i & 127;
    g_w2[i] = (n < 64) ? Wl[k * 64 + n] : Wr[k * 64 + (n - 64)];
}

// ---------------- layer1 GEMM via mma.sync bf16-split ----------------
#define TS 72
#define SM_AH 0
#define SM_AL (128 * TS)
#define SM_BH (2 * 128 * TS)
#define SM_BL (3 * 128 * TS)
#define SM_ELEMS (4 * 128 * TS)

__device__ __forceinline__ void mma16816(float* c, const uint32_t* a, uint32_t b0, uint32_t b1) {
    asm volatile(
        "mma.sync.aligned.m16n8k16.row.col.f32.bf16.bf16.f32 "
        "{%0,%1,%2,%3}, {%4,%5,%6,%7}, {%8,%9}, {%0,%1,%2,%3};"
        : "+f"(c[0]), "+f"(c[1]), "+f"(c[2]), "+f"(c[3])
        : "r"(a[0]), "r"(a[1]), "r"(a[2]), "r"(a[3]), "r"(b0), "r"(b1));
}

__global__ void __launch_bounds__(256, 2) k_gemm1() {
    extern __shared__ __nv_bfloat16 sm[];
    int tid = threadIdx.x;
    int wid = tid >> 5, lane = tid & 31;
    int m0 = blockIdx.y * 128, n0 = blockIdx.x * 128;
    int wm = (wid & 3) * 32, wn = (wid >> 2) * 64;
    int gr = lane >> 2, gc2 = (lane & 3) * 2;

    float acc[2][8][4];
#pragma unroll
    for (int mi = 0; mi < 2; mi++)
#pragma unroll
        for (int f = 0; f < 8; f++)
#pragma unroll
            for (int j = 0; j < 4; j++) acc[mi][f][j] = 0.f;

    for (int kc = 0; kc < 4; kc++) {
        int k0 = kc * 64;
#pragma unroll
        for (int u = tid; u < 1024; u += 256) {
            int r = u >> 3, i = u & 7;
            int m = m0 + r;
            uint4 vh = make_uint4(0u, 0u, 0u, 0u), vl = vh;
            if (m < Nn) {
                vh = ((const uint4*)(g_xhi + (size_t)m * FIN + k0))[i];
                vl = ((const uint4*)(g_xlo + (size_t)m * FIN + k0))[i];
            }
            *(uint4*)(sm + SM_AH + r * TS + i * 8) = vh;
            *(uint4*)(sm + SM_AL + r * TS + i * 8) = vl;
        }
#pragma unroll
        for (int u = tid; u < 1024; u += 256) {
            int r = u >> 3, i = u & 7;
            int n = n0 + r;
            uint4 vh = ((const uint4*)(g_whi + (size_t)n * FIN + k0))[i];
            uint4 vl = ((const uint4*)(g_wlo + (size_t)n * FIN + k0))[i];
            *(uint4*)(sm + SM_BH + r * TS + i * 8) = vh;
            *(uint4*)(sm + SM_BL + r * TS + i * 8) = vl;
        }
        __syncthreads();

#pragma unroll
        for (int kk = 0; kk < 64; kk += 16) {
            uint32_t ah[2][4], al[2][4];
#pragma unroll
            for (int mi = 0; mi < 2; mi++) {
                int r0 = wm + mi * 16 + gr;
                ah[mi][0] = *(const uint32_t*)(sm + SM_AH + (r0)     * TS + kk + gc2);
                ah[mi][1] = *(const uint32_t*)(sm + SM_AH + (r0 + 8) * TS + kk + gc2);
                ah[mi][2] = *(const uint32_t*)(sm + SM_AH + (r0)     * TS + kk + gc2 + 8);
                ah[mi][3] = *(const uint32_t*)(sm + SM_AH + (r0 + 8) * TS + kk + gc2 + 8);
                al[mi][0] = *(const uint32_t*)(sm + SM_AL + (r0)     * TS + kk + gc2);
                al[mi][1] = *(const uint32_t*)(sm + SM_AL + (r0 + 8) * TS + kk + gc2);
                al[mi][2] = *(const uint32_t*)(sm + SM_AL + (r0)     * TS + kk + gc2 + 8);
                al[mi][3] = *(const uint32_t*)(sm + SM_AL + (r0 + 8) * TS + kk + gc2 + 8);
            }
#pragma unroll
            for (int f = 0; f < 8; f++) {
                int nb = wn + f * 8 + gr;
                uint32_t bh0 = *(const uint32_t*)(sm + SM_BH + nb * TS + kk + gc2);
                uint32_t bh1 = *(const uint32_t*)(sm + SM_BH + nb * TS + kk + gc2 + 8);
                uint32_t bl0 = *(const uint32_t*)(sm + SM_BL + nb * TS + kk + gc2);
                uint32_t bl1 = *(const uint32_t*)(sm + SM_BL + nb * TS + kk + gc2 + 8);
#pragma unroll
                for (int mi = 0; mi < 2; mi++) {
                    mma16816(acc[mi][f], ah[mi], bh0, bh1);
                    mma16816(acc[mi][f], ah[mi], bl0, bl1);
                    mma16816(acc[mi][f], al[mi], bh0, bh1);
                }
            }
        }
        __syncthreads();
    }

#pragma unroll
    for (int mi = 0; mi < 2; mi++) {
        int r0 = m0 + wm + mi * 16 + gr;
#pragma unroll
        for (int f = 0; f < 8; f++) {
            int col = n0 + wn + f * 8 + gc2;
            if (r0 < Nn)
                *(float2*)(g_xlr + (size_t)r0 * NT + col) = make_float2(acc[mi][f][0], acc[mi][f][1]);
            if (r0 + 8 < Nn)
                *(float2*)(g_xlr + (size_t)(r0 + 8) * NT + col) = make_float2(acc[mi][f][2], acc[mi][f][3]);
        }
    }
}

// ---------------- fp32 tiled SGEMM (layer 2: h @ [W2l|W2r]) ----------------
__global__ void sgemm(const float* __restrict__ A, const float* __restrict__ B,
                      float* __restrict__ C, int M, int K, int Ncols) {
    const int BM = 128, BK = 16;
    __shared__ float As[BK][BM];
    __shared__ float Bs[BK][64];
    int tx = threadIdx.x, ty = threadIdx.y;
    int tid = ty * 16 + tx;
    int m0 = blockIdx.y * BM, n0 = blockIdx.x * 64;

    float acc[8][4];
#pragma unroll
    for (int r = 0; r < 8; r++)
#pragma unroll
        for (int c = 0; c < 4; c++) acc[r][c] = 0.f;

    for (int k0 = 0; k0 < K; k0 += BK) {
#pragma unroll
        for (int t = 0; t < 2; t++) {
            int i = tid + t * 256;
            int row = i >> 2, kq = i & 3;
            float4 v = make_float4(0.f, 0.f, 0.f, 0.f);
            int m = m0 + row;
            if (m < M) v = *(const float4*)(A + (size_t)m * K + k0 + kq * 4);
            As[kq * 4 + 0][row] = v.x;
            As[kq * 4 + 1][row] = v.y;
            As[kq * 4 + 2][row] = v.z;
            As[kq * 4 + 3][row] = v.w;
        }
        {
            int k = tid >> 4, nq = tid & 15;
            float4 v = *(const float4*)(B + (size_t)(k0 + k) * Ncols + n0 + nq * 4);
            *(float4*)&Bs[k][nq * 4] = v;
        }
        __syncthreads();
#pragma unroll
        for (int kk = 0; kk < BK; kk++) {
            float4 a0 = *(float4*)&As[kk][ty * 8];
            float4 a1 = *(float4*)&As[kk][ty * 8 + 4];
            float4 b  = *(float4*)&Bs[kk][tx * 4];
            float ar[8] = {a0.x, a0.y, a0.z, a0.w, a1.x, a1.y, a1.z, a1.w};
            float br[4] = {b.x, b.y, b.z, b.w};
#pragma unroll
            for (int r = 0; r < 8; r++)
#pragma unroll
                for (int c = 0; c < 4; c++) acc[r][c] = fmaf(ar[r], br[c], acc[r][c]);
        }
        __syncthreads();
    }
#pragma unroll
    for (int r = 0; r < 8; r++) {
        int m = m0 + ty * 8 + r;
        if (m < M) {
            float4 o = make_float4(acc[r][0], acc[r][1], acc[r][2], acc[r][3]);
            *(float4*)(C + (size_t)m * Ncols + n0 + tx * 4) = o;
        }
    }
}

// ---------------- layer1 fused attention, 2-edge unrolled ----------------
__global__ void k_gat1(const float* __restrict__ att, const float* __restrict__ bias,
                       const float* __restrict__ lng, const float* __restrict__ lnb) {
    int n = (blockIdx.x * blockDim.x + threadIdx.x) >> 5;
    int lane = threadIdx.x & 31;
    if (n >= Nn) return;

    const float4* xr = (const float4*)(g_xlr + (size_t)n * NT + 256);
    float4 b0 = xr[lane], b1 = xr[lane + 32];
    const float4* at = (const float4*)att;
    float4 w0 = at[lane], w1 = at[lane + 32];

    int beg = g_off[n], end = g_off[n + 1];

    float m_a = -1e30f, m_b = -1e30f, den_a = 0.f, den_b = 0.f;
    float4 acc0 = make_float4(0.f, 0.f, 0.f, 0.f);
    float4 acc1 = make_float4(0.f, 0.f, 0.f, 0.f);

    // prefetch first two edges
    float4 P0a, P0b, P1a, P1b;
    {
        int s0 = g_csrc[beg];
        const float4* p = (const float4*)(g_xlr + (size_t)s0 * NT);
        P0a = p[lane]; P0b = p[lane + 32];
        if (beg + 1 < end) {
            int s1 = g_csrc[beg + 1];
            const float4* q = (const float4*)(g_xlr + (size_t)s1 * NT);
            P1a = q[lane]; P1b = q[lane + 32];
        }
    }

    int k = beg;
    while (k + 1 < end) {
        float4 c0 = P0a, c1 = P0b, d0 = P1a, d1 = P1b;
        if (k + 2 < end) {
            int s = g_csrc[k + 2];
            const float4* p = (const float4*)(g_xlr + (size_t)s * NT);
            P0a = p[lane]; P0b = p[lane + 32];
        }
        if (k + 3 < end) {
            int s = g_csrc[k + 3];
            const float4* q = (const float4*)(g_xlr + (size_t)s * NT);
            P1a = q[lane]; P1b = q[lane + 32];
        }
        // scores for both edges, both head-groups
        float p0 = 0.f, p1 = 0.f, q0 = 0.f, q1 = 0.f, z;
        z = c0.x + b0.x; p0 = fmaf(lrelu(z), w0.x, p0);
        z = c0.y + b0.y; p0 = fmaf(lrelu(z), w0.y, p0);
        z = c0.z + b0.z; p0 = fmaf(lrelu(z), w0.z, p0);
        z = c0.w + b0.w; p0 = fmaf(lrelu(z), w0.w, p0);
        z = c1.x + b1.x; p1 = fmaf(lrelu(z), w1.x, p1);
        z = c1.y + b1.y; p1 = fmaf(lrelu(z), w1.y, p1);
        z = c1.z + b1.z; p1 = fmaf(lrelu(z), w1.z, p1);
        z = c1.w + b1.w; p1 = fmaf(lrelu(z), w1.w, p1);
        z = d0.x + b0.x; q0 = fmaf(lrelu(z), w0.x, q0);
        z = d0.y + b0.y; q0 = fmaf(lrelu(z), w0.y, q0);
        z = d0.z + b0.z; q0 = fmaf(lrelu(z), w0.z, q0);
        z = d0.w + b0.w; q0 = fmaf(lrelu(z), w0.w, q0);
        z = d1.x + b1.x; q1 = fmaf(lrelu(z), w1.x, q1);
        z = d1.y + b1.y; q1 = fmaf(lrelu(z), w1.y, q1);
        z = d1.z + b1.z; q1 = fmaf(lrelu(z), w1.z, q1);
        z = d1.w + b1.w; q1 = fmaf(lrelu(z), w1.w, q1);
#pragma unroll
        for (int o = 8; o > 0; o >>= 1) {
            p0 += __shfl_xor_sync(0xffffffffu, p0, o, 16);
            p1 += __shfl_xor_sync(0xffffffffu, p1, o, 16);
            q0 += __shfl_xor_sync(0xffffffffu, q0, o, 16);
            q1 += __shfl_xor_sync(0xffffffffu, q1, o, 16);
        }
        // merged online softmax update: 2 edges per rescale
        float mn = fmaxf(m_a, fmaxf(p0, q0));
        float sc = __expf(m_a - mn);
        float wp = __expf(p0 - mn);
        float wq = __expf(q0 - mn);
        den_a = den_a * sc + wp + wq;
        acc0.x = acc0.x * sc + wp * c0.x + wq * d0.x;
        acc0.y = acc0.y * sc + wp * c0.y + wq * d0.y;
        acc0.z = acc0.z * sc + wp * c0.z + wq * d0.z;
        acc0.w = acc0.w * sc + wp * c0.w + wq * d0.w;
        m_a = mn;

        mn = fmaxf(m_b, fmaxf(p1, q1));
        sc = __expf(m_b - mn);
        wp = __expf(p1 - mn);
        wq = __expf(q1 - mn);
        den_b = den_b * sc + wp + wq;
        acc1.x = acc1.x * sc + wp * c1.x + wq * d1.x;
        acc1.y = acc1.y * sc + wp * c1.y + wq * d1.y;
        acc1.z = acc1.z * sc + wp * c1.z + wq * d1.z;
        acc1.w = acc1.w * sc + wp * c1.w + wq * d1.w;
        m_b = mn;

        k += 2;
    }
    if (k < end) {   // odd tail
        float4 c0 = P0a, c1 = P0b;
        float p0 = 0.f, p1 = 0.f, z;
        z = c0.x + b0.x; p0 = fmaf(lrelu(z), w0.x, p0);
        z = c0.y + b0.y; p0 = fmaf(lrelu(z), w0.y, p0);
        z = c0.z + b0.z; p0 = fmaf(lrelu(z), w0.z, p0);
        z = c0.w + b0.w; p0 = fmaf(lrelu(z), w0.w, p0);
        z = c1.x + b1.x; p1 = fmaf(lrelu(z), w1.x, p1);
        z = c1.y + b1.y; p1 = fmaf(lrelu(z), w1.y, p1);
        z = c1.z + b1.z; p1 = fmaf(lrelu(z), w1.z, p1);
        z = c1.w + b1.w; p1 = fmaf(lrelu(z), w1.w, p1);
#pragma unroll
        for (int o = 8; o > 0; o >>= 1) {
            p0 += __shfl_xor_sync(0xffffffffu, p0, o, 16);
            p1 += __shfl_xor_sync(0xffffffffu, p1, o, 16);
        }
        float mn = fmaxf(m_a, p0);
        float sc = __expf(m_a - mn);
        float wp = __expf(p0 - mn);
        den_a = den_a * sc + wp;
        acc0.x = acc0.x * sc + wp * c0.x;
        acc0.y = acc0.y * sc + wp * c0.y;
        acc0.z = acc0.z * sc + wp * c0.z;
        acc0.w = acc0.w * sc + wp * c0.w;
        m_a = mn;

        mn = fmaxf(m_b, p1);
        sc = __expf(m_b - mn);
        wp = __expf(p1 - mn);
        den_b = den_b * sc + wp;
        acc1.x = acc1.x * sc + wp * c1.x;
        acc1.y = acc1.y * sc + wp * c1.y;
        acc1.z = acc1.z * sc + wp * c1.z;
        acc1.w = acc1.w * sc + wp * c1.w;
        m_b = mn;
    }

    float ra = 1.f / (den_a + 1e-16f);
    float rb = 1.f / (den_b + 1e-16f);
    float4 sum;
    sum.x = acc0.x * ra + acc1.x * rb;
    sum.y = acc0.y * ra + acc1.y * rb;
    sum.z = acc0.z * ra + acc1.z * rb;
    sum.w = acc0.w * ra + acc1.w * rb;
    sum.x += __shfl_xor_sync(0xffffffffu, sum.x, 16);
    sum.y += __shfl_xor_sync(0xffffffffu, sum.y, 16);
    sum.z += __shfl_xor_sync(0xffffffffu, sum.z, 16);
    sum.w += __shfl_xor_sync(0xffffffffu, sum.w, 16);

    int q = lane & 15;
    float4 bv = ((const float4*)bias)[q];
    float4 v;
    v.x = 0.25f * sum.x + bv.x;
    v.y = 0.25f * sum.y + bv.y;
    v.z = 0.25f * sum.z + bv.z;
    v.w = 0.25f * sum.w + bv.w;

    float ssum = v.x + v.y + v.z + v.w;
#pragma unroll
    for (int o = 16; o > 0; o >>= 1) ssum += __shfl_xor_sync(0xffffffffu, ssum, o);
    float mu = ssum * (1.f / 128.f);
    float dx = v.x - mu, dy = v.y - mu, dz = v.z - mu, dw = v.w - mu;
    float sq = dx * dx + dy * dy + dz * dz + dw * dw;
#pragma unroll
    for (int o = 16; o > 0; o >>= 1) sq += __shfl_xor_sync(0xffffffffu, sq, o);
    float inv = rsqrtf(sq * (1.f / 128.f) + 1e-5f);

    if (lane < 16) {
        float4 gv = ((const float4*)lng)[q];
        float4 b2 = ((const float4*)lnb)[q];
        float4 o;
        o.x = fmaxf(dx * inv * gv.x + b2.x, 0.f);
        o.y = fmaxf(dy * inv * gv.y + b2.y, 0.f);
        o.z = fmaxf(dz * inv * gv.z + b2.z, 0.f);
        o.w = fmaxf(dw * inv * gv.w + b2.w, 0.f);
        *(float4*)(g_h + (size_t)n * HID + 4 * q) = o;
    }
}

// ---------------- layer2 fused attention, 2-edge unrolled ----------------
__global__ void k_gat2(const float* __restrict__ att, const float* __restrict__ bias,
                       const float* __restrict__ lng, const float* __restrict__ lnb,
                       float* __restrict__ out) {
    int n = (blockIdx.x * blockDim.x + threadIdx.x) >> 5;
    int lane = threadIdx.x & 31;
    if (n >= Nn) return;

    float2 b = ((const float2*)(g_xlr2 + (size_t)n * 128 + 64))[lane];
    float2 w = ((const float2*)att)[lane];

    int beg = g_off[n], end = g_off[n + 1];
    float m = -1e30f, den = 0.f;
    float2 acc = make_float2(0.f, 0.f);

    float2 P0, P1;
    {
        int s0 = g_csrc[beg];
        P0 = ((const float2*)(g_xlr2 + (size_t)s0 * 128))[lane];
        if (beg + 1 < end) {
            int s1 = g_csrc[beg + 1];
            P1 = ((const float2*)(g_xlr2 + (size_t)s1 * 128))[lane];
        }
    }

    int k = beg;
    while (k + 1 < end) {
        float2 c = P0, d = P1;
        if (k + 2 < end) {
            int s = g_csrc[k + 2];
            P0 = ((const float2*)(g_xlr2 + (size_t)s * 128))[lane];
        }
        if (k + 3 < end) {
            int s = g_csrc[k + 3];
            P1 = ((const float2*)(g_xlr2 + (size_t)s * 128))[lane];
        }
        float p = lrelu(c.x + b.x) * w.x + lrelu(c.y + b.y) * w.y;
        float q = lrelu(d.x + b.x) * w.x + lrelu(d.y + b.y) * w.y;
#pragma unroll
        for (int o = 16; o > 0; o >>= 1) {
            p += __shfl_xor_sync(0xffffffffu, p, o);
            q += __shfl_xor_sync(0xffffffffu, q, o);
        }
        float mn = fmaxf(m, fmaxf(p, q));
        float sc = __expf(m - mn);
        float wp = __expf(p - mn);
        float wq = __expf(q - mn);
        den = den * sc + wp + wq;
        acc.x = acc.x * sc + wp * c.x + wq * d.x;
        acc.y = acc.y * sc + wp * c.y + wq * d.y;
        m = mn;
        k += 2;
    }
    if (k < end) {
        float2 c = P0;
        float p = lrelu(c.x + b.x) * w.x + lrelu(c.y + b.y) * w.y;
#pragma unroll
        for (int o = 16; o > 0; o >>= 1) p += __shfl_xor_sync(0xffffffffu, p, o);
        float mn = fmaxf(m, p);
        float sc = __expf(m - mn);
        float wp = __expf(p - mn);
        den = den * sc + wp;
        acc.x = acc.x * sc + wp * c.x;
        acc.y = acc.y * sc + wp * c.y;
        m = mn;
    }

    float r = 1.f / (den + 1e-16f);
    float2 bv = ((const float2*)bias)[lane];
    float vx = acc.x * r + bv.x;
    float vy = acc.y * r + bv.y;

    float ssum = vx + vy;
#pragma unroll
    for (int o = 16; o > 0; o >>= 1) ssum += __shfl_xor_sync(0xffffffffu, ssum, o);
    float mu = ssum * (1.f / 64.f);
    float dx = vx - mu, dy = vy - mu;
    float sq = dx * dx + dy * dy;
#pragma unroll
    for (int o = 16; o > 0; o >>= 1) sq += __shfl_xor_sync(0xffffffffu, sq, o);
    float inv = rsqrtf(sq * (1.f / 64.f) + 1e-5f);

    float2 gv = ((const float2*)lng)[lane];
    float2 b2 = ((const float2*)lnb)[lane];
    float2 o;
    o.x = dx * inv * gv.x + b2.x;
    o.y = dy * inv * gv.y + b2.y;
    ((float2*)(out + (size_t)n * HID))[lane] = o;
}

// ---------------- launch ----------------
extern "C" void kernel_launch(void* const* d_in, const int* in_sizes, int n_in,
                              void* d_out, int out_size) {
    const float* x    = (const float*)d_in[0];
    const int*   ei   = (const int*)d_in[1];
    const float* W1l  = (const float*)d_in[2];
    const float* W1r  = (const float*)d_in[3];
    const float* att1 = (const float*)d_in[4];
    const float* b1   = (const float*)d_in[5];
    const float* ln1g = (const float*)d_in[6];
    const float* ln1b = (const float*)d_in[7];
    const float* W2l  = (const float*)d_in[8];
    const float* W2r  = (const float*)d_in[9];
    const float* att2 = (const float*)d_in[10];
    const float* b2   = (const float*)d_in[11];
    const float* ln2g = (const float*)d_in[12];
    const float* ln2b = (const float*)d_in[13];
    float* out = (float*)d_out;

    const int* srcp = ei;
    const int* dstp = ei + Ein;

    float *hp, *w2p, *xlr2p;
    cudaGetSymbolAddress((void**)&hp,    g_h);
    cudaGetSymbolAddress((void**)&w2p,   g_w2);
    cudaGetSymbolAddress((void**)&xlr2p, g_xlr2);

    const int T = 256;

    // CSR build (shared by both layers)
    k_zero<<<(Nn + T - 1) / T, T>>>();
    k_hist<<<(ET + T - 1) / T, T>>>(dstp);
    k_scan<<<1, 1024>>>();
    k_fill<<<(ET + T - 1) / T, T>>>(srcp, dstp);

    // bf16 hi/lo conversions + layer2 weight pack
    k_convw<<<(NT * FIN + T - 1) / T, T>>>(W1l, W1r);
    k_convx<<<(Nn * FIN + T - 1) / T, T>>>(x);
    k_packw2<<<(64 * 128 + T - 1) / T, T>>>(W2l, W2r);

    // layer1 GEMM on tensor cores via mma.sync (bf16-split, xl|xr fused, N=512)
    size_t smbytes = SM_ELEMS * sizeof(__nv_bfloat16);   // 73728
    cudaFuncSetAttribute(k_gemm1, cudaFuncAttributeMaxDynamicSharedMemorySize, (int)smbytes);
    dim3 gg(NT / 128, (Nn + 127) / 128);
    k_gemm1<<<gg, 256, smbytes>>>();

    // layer1 fused attention + LN + relu
    k_gat1<<<(Nn * 32 + T - 1) / T, T>>>(att1, b1, ln1g, ln1b);

    // layer2 GEMM: [50000,64] @ [64,128] (fp32, fused l|r)
    dim3 g2(2, (Nn + 127) / 128), blk(16, 16);
    sgemm<<<g2, blk>>>(hp, w2p, xlr2p, Nn, HID, 128);

    // layer2 fused attention + LN -> out
    k_gat2<<<(Nn * 32 + T - 1) / T, T>>>(att2, b2, ln2g, ln2b, out);
}

// round 11
// speedup vs baseline: 2.8992x; 1.1714x over previous
#include <cuda_runtime.h>
#include <cuda_fp16.h>
#include <math.h>
#include <stdint.h>

#define Nn  50000
#define Ein 800000
#define ET  850000      // Ein + Nn self loops
#define FIN 256
#define HID 64
#define H1  4
#define NT  512         // xl (256) ++ xr (256)

// ---------------- scratch (device globals; no allocation allowed) ----------
__device__ float g_xlr[(size_t)Nn * NT];    // layer1 projections [xl | xr]
__device__ __align__(16) __half g_xh [Nn * FIN];         // x rounded to fp16
__device__ __align__(16) __half g_whi[NT * FIN];         // Wt[n][k] fp16 hi
__device__ __align__(16) __half g_wlo[NT * FIN];         // Wt[n][k] fp16 lo
__device__ float g_h[Nn * HID];
__device__ float g_w2[64 * 128];            // packed [W2l | W2r], B[k][n]
__device__ float g_xlr2[(size_t)Nn * 128];  // layer2 projections [xl2 | xr2]

__device__ int g_deg[Nn];
__device__ int g_cur[Nn];
__device__ int g_off[Nn + 1];
__device__ int g_csrc[ET];

__device__ __forceinline__ float lrelu(float z) {
    return fmaxf(z, 0.f) + 0.2f * fminf(z, 0.f);
}

// ---------------- CSR build ----------------
__global__ void k_zero() {
    int i = blockIdx.x * blockDim.x + threadIdx.x;
    if (i < Nn) { g_deg[i] = 0; g_cur[i] = 0; }
}

__global__ void k_hist(const int* __restrict__ dst) {
    int e = blockIdx.x * blockDim.x + threadIdx.x;
    if (e >= ET) return;
    int d = (e < Ein) ? dst[e] : (e - Ein);
    atomicAdd(&g_deg[d], 1);
}

__global__ void k_scan() {   // single block, 1024 threads, 4 elems/thread
    __shared__ int wsum[32];
    __shared__ int carry_s;
    int t = threadIdx.x;
    if (t == 0) carry_s = 0;
    __syncthreads();
    for (int base = 0; base < Nn; base += 4096) {
        int i0 = base + t * 4;
        int v0 = (i0 + 0 < Nn) ? g_deg[i0 + 0] : 0;
        int v1 = (i0 + 1 < Nn) ? g_deg[i0 + 1] : 0;
        int v2 = (i0 + 2 < Nn) ? g_deg[i0 + 2] : 0;
        int v3 = (i0 + 3 < Nn) ? g_deg[i0 + 3] : 0;
        int tsum = v0 + v1 + v2 + v3;
        int x = tsum;
#pragma unroll
        for (int o = 1; o < 32; o <<= 1) {
            int y = __shfl_up_sync(0xffffffffu, x, o);
            if ((t & 31) >= o) x += y;
        }
        if ((t & 31) == 31) wsum[t >> 5] = x;
        __syncthreads();
        if (t < 32) {
            int wv = wsum[t];
#pragma unroll
            for (int o = 1; o < 32; o <<= 1) {
                int y = __shfl_up_sync(0xffffffffu, wv, o);
                if (t >= o) wv += y;
            }
            wsum[t] = wv;
        }
        __syncthreads();
        int excl = x - tsum + ((t >> 5) ? wsum[(t >> 5) - 1] : 0) + carry_s;
        if (i0 + 0 < Nn) g_off[i0 + 0] = excl;
        if (i0 + 1 < Nn) g_off[i0 + 1] = excl + v0;
        if (i0 + 2 < Nn) g_off[i0 + 2] = excl + v0 + v1;
        if (i0 + 3 < Nn) g_off[i0 + 3] = excl + v0 + v1 + v2;
        int tot = wsum[31];
        __syncthreads();
        if (t == 0) carry_s += tot;
        __syncthreads();
    }
    if (t == 0) g_off[Nn] = carry_s;
}

__global__ void k_fill(const int* __restrict__ src, const int* __restrict__ dst) {
    int e = blockIdx.x * blockDim.x + threadIdx.x;
    if (e >= ET) return;
    int s, d;
    if (e < Ein) { s = src[e]; d = dst[e]; }
    else         { s = e - Ein; d = s; }
    int p = atomicAdd(&g_cur[d], 1);
    g_csrc[g_off[d] + p] = s;
}

// ---------------- conversions ----------------
__global__ void k_convx(const float* __restrict__ x) {
    int i = blockIdx.x * blockDim.x + threadIdx.x;
    if (i >= Nn * FIN) return;
    g_xh[i] = __float2half(x[i]);
}

__global__ void k_convw(const float* __restrict__ Wl, const float* __restrict__ Wr) {
    int i = blockIdx.x * blockDim.x + threadIdx.x;
    if (i >= NT * FIN) return;
    int n = i >> 8, k = i & 255;   // FIN = 256
    float v = (n < 256) ? Wl[k * 256 + n] : Wr[k * 256 + (n - 256)];
    __half hi = __float2half(v);
    g_whi[i] = hi;
    g_wlo[i] = __float2half(v - __half2float(hi));
}

__global__ void k_packw2(const float* __restrict__ Wl, const float* __restrict__ Wr) {
    int i = blockIdx.x * blockDim.x + threadIdx.x;
    if (i >= 64 * 128) return;
    int k = i >> 7, n = i & 127;
    g_w2[i] = (n < 64) ? Wl[k * 64 + n] : Wr[k * 64 + (n - 64)];
}

// ---------------- layer1 GEMM via mma.sync fp16 2-term ----------------
// C[50000, 512] = Xh[50000, 256] @ (Whi + Wlo)^T.  CTA 128x128, 8 warps 32x64.
#define TS 72
#define SM_A  0
#define SM_BH (128 * TS)
#define SM_BL (2 * 128 * TS)
#define SM_ELEMS (3 * 128 * TS)

__device__ __forceinline__ void mma16816h(float* c, const uint32_t* a, uint32_t b0, uint32_t b1) {
    asm volatile(
        "mma.sync.aligned.m16n8k16.row.col.f32.f16.f16.f32 "
        "{%0,%1,%2,%3}, {%4,%5,%6,%7}, {%8,%9}, {%0,%1,%2,%3};"
        : "+f"(c[0]), "+f"(c[1]), "+f"(c[2]), "+f"(c[3])
        : "r"(a[0]), "r"(a[1]), "r"(a[2]), "r"(a[3]), "r"(b0), "r"(b1));
}

__global__ void __launch_bounds__(256, 2) k_gemm1() {
    extern __shared__ __half sm[];
    int tid = threadIdx.x;
    int wid = tid >> 5, lane = tid & 31;
    int m0 = blockIdx.y * 128, n0 = blockIdx.x * 128;
    int wm = (wid & 3) * 32, wn = (wid >> 2) * 64;
    int gr = lane >> 2, gc2 = (lane & 3) * 2;

    float acc[2][8][4];
#pragma unroll
    for (int mi = 0; mi < 2; mi++)
#pragma unroll
        for (int f = 0; f < 8; f++)
#pragma unroll
            for (int j = 0; j < 4; j++) acc[mi][f][j] = 0.f;

    for (int kc = 0; kc < 4; kc++) {
        int k0 = kc * 64;
        // A tile: 128 rows x 64 fp16 (1024 uint4)
#pragma unroll
        for (int u = tid; u < 1024; u += 256) {
            int r = u >> 3, i = u & 7;
            int m = m0 + r;
            uint4 v = make_uint4(0u, 0u, 0u, 0u);
            if (m < Nn) v = ((const uint4*)(g_xh + (size_t)m * FIN + k0))[i];
            *(uint4*)(sm + SM_A + r * TS + i * 8) = v;
        }
        // B tiles hi+lo: 128 n-rows x 64 fp16
#pragma unroll
        for (int u = tid; u < 1024; u += 256) {
            int r = u >> 3, i = u & 7;
            int n = n0 + r;
            uint4 vh = ((const uint4*)(g_whi + (size_t)n * FIN + k0))[i];
            uint4 vl = ((const uint4*)(g_wlo + (size_t)n * FIN + k0))[i];
            *(uint4*)(sm + SM_BH + r * TS + i * 8) = vh;
            *(uint4*)(sm + SM_BL + r * TS + i * 8) = vl;
        }
        __syncthreads();

#pragma unroll
        for (int kk = 0; kk < 64; kk += 16) {
            uint32_t a[2][4];
#pragma unroll
            for (int mi = 0; mi < 2; mi++) {
                int r0 = wm + mi * 16 + gr;
                a[mi][0] = *(const uint32_t*)(sm + SM_A + (r0)     * TS + kk + gc2);
                a[mi][1] = *(const uint32_t*)(sm + SM_A + (r0 + 8) * TS + kk + gc2);
                a[mi][2] = *(const uint32_t*)(sm + SM_A + (r0)     * TS + kk + gc2 + 8);
                a[mi][3] = *(const uint32_t*)(sm + SM_A + (r0 + 8) * TS + kk + gc2 + 8);
            }
#pragma unroll
            for (int f = 0; f < 8; f++) {
                int nb = wn + f * 8 + gr;
                uint32_t bh0 = *(const uint32_t*)(sm + SM_BH + nb * TS + kk + gc2);
                uint32_t bh1 = *(const uint32_t*)(sm + SM_BH + nb * TS + kk + gc2 + 8);
                uint32_t bl0 = *(const uint32_t*)(sm + SM_BL + nb * TS + kk + gc2);
                uint32_t bl1 = *(const uint32_t*)(sm + SM_BL + nb * TS + kk + gc2 + 8);
#pragma unroll
                for (int mi = 0; mi < 2; mi++) {
                    mma16816h(acc[mi][f], a[mi], bh0, bh1);
                    mma16816h(acc[mi][f], a[mi], bl0, bl1);
                }
            }
        }
        __syncthreads();
    }

#pragma unroll
    for (int mi = 0; mi < 2; mi++) {
        int r0 = m0 + wm + mi * 16 + gr;
#pragma unroll
        for (int f = 0; f < 8; f++) {
            int col = n0 + wn + f * 8 + gc2;
            if (r0 < Nn)
                *(float2*)(g_xlr + (size_t)r0 * NT + col) = make_float2(acc[mi][f][0], acc[mi][f][1]);
            if (r0 + 8 < Nn)
                *(float2*)(g_xlr + (size_t)(r0 + 8) * NT + col) = make_float2(acc[mi][f][2], acc[mi][f][3]);
        }
    }
}

// ---------------- fp32 tiled SGEMM (layer 2: h @ [W2l|W2r]) ----------------
__global__ void sgemm(const float* __restrict__ A, const float* __restrict__ B,
                      float* __restrict__ C, int M, int K, int Ncols) {
    const int BM = 128, BK = 16;
    __shared__ float As[BK][BM];
    __shared__ float Bs[BK][64];
    int tx = threadIdx.x, ty = threadIdx.y;
    int tid = ty * 16 + tx;
    int m0 = blockIdx.y * BM, n0 = blockIdx.x * 64;

    float acc[8][4];
#pragma unroll
    for (int r = 0; r < 8; r++)
#pragma unroll
        for (int c = 0; c < 4; c++) acc[r][c] = 0.f;

    for (int k0 = 0; k0 < K; k0 += BK) {
#pragma unroll
        for (int t = 0; t < 2; t++) {
            int i = tid + t * 256;
            int row = i >> 2, kq = i & 3;
            float4 v = make_float4(0.f, 0.f, 0.f, 0.f);
            int m = m0 + row;
            if (m < M) v = *(const float4*)(A + (size_t)m * K + k0 + kq * 4);
            As[kq * 4 + 0][row] = v.x;
            As[kq * 4 + 1][row] = v.y;
            As[kq * 4 + 2][row] = v.z;
            As[kq * 4 + 3][row] = v.w;
        }
        {
            int k = tid >> 4, nq = tid & 15;
            float4 v = *(const float4*)(B + (size_t)(k0 + k) * Ncols + n0 + nq * 4);
            *(float4*)&Bs[k][nq * 4] = v;
        }
        __syncthreads();
#pragma unroll
        for (int kk = 0; kk < BK; kk++) {
            float4 a0 = *(float4*)&As[kk][ty * 8];
            float4 a1 = *(float4*)&As[kk][ty * 8 + 4];
            float4 b  = *(float4*)&Bs[kk][tx * 4];
            float ar[8] = {a0.x, a0.y, a0.z, a0.w, a1.x, a1.y, a1.z, a1.w};
            float br[4] = {b.x, b.y, b.z, b.w};
#pragma unroll
            for (int r = 0; r < 8; r++)
#pragma unroll
                for (int c = 0; c < 4; c++) acc[r][c] = fmaf(ar[r], br[c], acc[r][c]);
        }
        __syncthreads();
    }
#pragma unroll
    for (int r = 0; r < 8; r++) {
        int m = m0 + ty * 8 + r;
        if (m < M) {
            float4 o = make_float4(acc[r][0], acc[r][1], acc[r][2], acc[r][3]);
            *(float4*)(C + (size_t)m * Ncols + n0 + tx * 4) = o;
        }
    }
}

// ---------------- layer1 fused attention, 2-edge unrolled ----------------
__global__ void k_gat1(const float* __restrict__ att, const float* __restrict__ bias,
                       const float* __restrict__ lng, const float* __restrict__ lnb) {
    int n = (blockIdx.x * blockDim.x + threadIdx.x) >> 5;
    int lane = threadIdx.x & 31;
    if (n >= Nn) return;

    const float4* xr = (const float4*)(g_xlr + (size_t)n * NT + 256);
    float4 b0 = xr[lane], b1 = xr[lane + 32];
    const float4* at = (const float4*)att;
    float4 w0 = at[lane], w1 = at[lane + 32];

    int beg = g_off[n], end = g_off[n + 1];

    float m_a = -1e30f, m_b = -1e30f, den_a = 0.f, den_b = 0.f;
    float4 acc0 = make_float4(0.f, 0.f, 0.f, 0.f);
    float4 acc1 = make_float4(0.f, 0.f, 0.f, 0.f);

    float4 P0a, P0b, P1a, P1b;
    {
        int s0 = g_csrc[beg];
        const float4* p = (const float4*)(g_xlr + (size_t)s0 * NT);
        P0a = p[lane]; P0b = p[lane + 32];
        if (beg + 1 < end) {
            int s1 = g_csrc[beg + 1];
            const float4* q = (const float4*)(g_xlr + (size_t)s1 * NT);
            P1a = q[lane]; P1b = q[lane + 32];
        }
    }

    int k = beg;
    while (k + 1 < end) {
        float4 c0 = P0a, c1 = P0b, d0 = P1a, d1 = P1b;
        if (k + 2 < end) {
            int s = g_csrc[k + 2];
            const float4* p = (const float4*)(g_xlr + (size_t)s * NT);
            P0a = p[lane]; P0b = p[lane + 32];
        }
        if (k + 3 < end) {
            int s = g_csrc[k + 3];
            const float4* q = (const float4*)(g_xlr + (size_t)s * NT);
            P1a = q[lane]; P1b = q[lane + 32];
        }
        float p0 = 0.f, p1 = 0.f, q0 = 0.f, q1 = 0.f, z;
        z = c0.x + b0.x; p0 = fmaf(lrelu(z), w0.x, p0);
        z = c0.y + b0.y; p0 = fmaf(lrelu(z), w0.y, p0);
        z = c0.z + b0.z; p0 = fmaf(lrelu(z), w0.z, p0);
        z = c0.w + b0.w; p0 = fmaf(lrelu(z), w0.w, p0);
        z = c1.x + b1.x; p1 = fmaf(lrelu(z), w1.x, p1);
        z = c1.y + b1.y; p1 = fmaf(lrelu(z), w1.y, p1);
        z = c1.z + b1.z; p1 = fmaf(lrelu(z), w1.z, p1);
        z = c1.w + b1.w; p1 = fmaf(lrelu(z), w1.w, p1);
        z = d0.x + b0.x; q0 = fmaf(lrelu(z), w0.x, q0);
        z = d0.y + b0.y; q0 = fmaf(lrelu(z), w0.y, q0);
        z = d0.z + b0.z; q0 = fmaf(lrelu(z), w0.z, q0);
        z = d0.w + b0.w; q0 = fmaf(lrelu(z), w0.w, q0);
        z = d1.x + b1.x; q1 = fmaf(lrelu(z), w1.x, q1);
        z = d1.y + b1.y; q1 = fmaf(lrelu(z), w1.y, q1);
        z = d1.z + b1.z; q1 = fmaf(lrelu(z), w1.z, q1);
        z = d1.w + b1.w; q1 = fmaf(lrelu(z), w1.w, q1);
#pragma unroll
        for (int o = 8; o > 0; o >>= 1) {
            p0 += __shfl_xor_sync(0xffffffffu, p0, o, 16);
            p1 += __shfl_xor_sync(0xffffffffu, p1, o, 16);
            q0 += __shfl_xor_sync(0xffffffffu, q0, o, 16);
            q1 += __shfl_xor_sync(0xffffffffu, q1, o, 16);
        }
        float mn = fmaxf(m_a, fmaxf(p0, q0));
        float sc = __expf(m_a - mn);
        float wp = __expf(p0 - mn);
        float wq = __expf(q0 - mn);
        den_a = den_a * sc + wp + wq;
        acc0.x = acc0.x * sc + wp * c0.x + wq * d0.x;
        acc0.y = acc0.y * sc + wp * c0.y + wq * d0.y;
        acc0.z = acc0.z * sc + wp * c0.z + wq * d0.z;
        acc0.w = acc0.w * sc + wp * c0.w + wq * d0.w;
        m_a = mn;

        mn = fmaxf(m_b, fmaxf(p1, q1));
        sc = __expf(m_b - mn);
        wp = __expf(p1 - mn);
        wq = __expf(q1 - mn);
        den_b = den_b * sc + wp + wq;
        acc1.x = acc1.x * sc + wp * c1.x + wq * d1.x;
        acc1.y = acc1.y * sc + wp * c1.y + wq * d1.y;
        acc1.z = acc1.z * sc + wp * c1.z + wq * d1.z;
        acc1.w = acc1.w * sc + wp * c1.w + wq * d1.w;
        m_b = mn;

        k += 2;
    }
    if (k < end) {
        float4 c0 = P0a, c1 = P0b;
        float p0 = 0.f, p1 = 0.f, z;
        z = c0.x + b0.x; p0 = fmaf(lrelu(z), w0.x, p0);
        z = c0.y + b0.y; p0 = fmaf(lrelu(z), w0.y, p0);
        z = c0.z + b0.z; p0 = fmaf(lrelu(z), w0.z, p0);
        z = c0.w + b0.w; p0 = fmaf(lrelu(z), w0.w, p0);
        z = c1.x + b1.x; p1 = fmaf(lrelu(z), w1.x, p1);
        z = c1.y + b1.y; p1 = fmaf(lrelu(z), w1.y, p1);
        z = c1.z + b1.z; p1 = fmaf(lrelu(z), w1.z, p1);
        z = c1.w + b1.w; p1 = fmaf(lrelu(z), w1.w, p1);
#pragma unroll
        for (int o = 8; o > 0; o >>= 1) {
            p0 += __shfl_xor_sync(0xffffffffu, p0, o, 16);
            p1 += __shfl_xor_sync(0xffffffffu, p1, o, 16);
        }
        float mn = fmaxf(m_a, p0);
        float sc = __expf(m_a - mn);
        float wp = __expf(p0 - mn);
        den_a = den_a * sc + wp;
        acc0.x = acc0.x * sc + wp * c0.x;
        acc0.y = acc0.y * sc + wp * c0.y;
        acc0.z = acc0.z * sc + wp * c0.z;
        acc0.w = acc0.w * sc + wp * c0.w;
        m_a = mn;

        mn = fmaxf(m_b, p1);
        sc = __expf(m_b - mn);
        wp = __expf(p1 - mn);
        den_b = den_b * sc + wp;
        acc1.x = acc1.x * sc + wp * c1.x;
        acc1.y = acc1.y * sc + wp * c1.y;
        acc1.z = acc1.z * sc + wp * c1.z;
        acc1.w = acc1.w * sc + wp * c1.w;
        m_b = mn;
    }

    float ra = 1.f / (den_a + 1e-16f);
    float rb = 1.f / (den_b + 1e-16f);
    float4 sum;
    sum.x = acc0.x * ra + acc1.x * rb;
    sum.y = acc0.y * ra + acc1.y * rb;
    sum.z = acc0.z * ra + acc1.z * rb;
    sum.w = acc0.w * ra + acc1.w * rb;
    sum.x += __shfl_xor_sync(0xffffffffu, sum.x, 16);
    sum.y += __shfl_xor_sync(0xffffffffu, sum.y, 16);
    sum.z += __shfl_xor_sync(0xffffffffu, sum.z, 16);
    sum.w += __shfl_xor_sync(0xffffffffu, sum.w, 16);

    int q = lane & 15;
    float4 bv = ((const float4*)bias)[q];
    float4 v;
    v.x = 0.25f * sum.x + bv.x;
    v.y = 0.25f * sum.y + bv.y;
    v.z = 0.25f * sum.z + bv.z;
    v.w = 0.25f * sum.w + bv.w;

    float ssum = v.x + v.y + v.z + v.w;
#pragma unroll
    for (int o = 16; o > 0; o >>= 1) ssum += __shfl_xor_sync(0xffffffffu, ssum, o);
    float mu = ssum * (1.f / 128.f);
    float dx = v.x - mu, dy = v.y - mu, dz = v.z - mu, dw = v.w - mu;
    float sq = dx * dx + dy * dy + dz * dz + dw * dw;
#pragma unroll
    for (int o = 16; o > 0; o >>= 1) sq += __shfl_xor_sync(0xffffffffu, sq, o);
    float inv = rsqrtf(sq * (1.f / 128.f) + 1e-5f);

    if (lane < 16) {
        float4 gv = ((const float4*)lng)[q];
        float4 b2 = ((const float4*)lnb)[q];
        float4 o;
        o.x = fmaxf(dx * inv * gv.x + b2.x, 0.f);
        o.y = fmaxf(dy * inv * gv.y + b2.y, 0.f);
        o.z = fmaxf(dz * inv * gv.z + b2.z, 0.f);
        o.w = fmaxf(dw * inv * gv.w + b2.w, 0.f);
        *(float4*)(g_h + (size_t)n * HID + 4 * q) = o;
    }
}

// ---------------- layer2 fused attention, 2-edge unrolled ----------------
__global__ void k_gat2(const float* __restrict__ att, const float* __restrict__ bias,
                       const float* __restrict__ lng, const float* __restrict__ lnb,
                       float* __restrict__ out) {
    int n = (blockIdx.x * blockDim.x + threadIdx.x) >> 5;
    int lane = threadIdx.x & 31;
    if (n >= Nn) return;

    float2 b = ((const float2*)(g_xlr2 + (size_t)n * 128 + 64))[lane];
    float2 w = ((const float2*)att)[lane];

    int beg = g_off[n], end = g_off[n + 1];
    float m = -1e30f, den = 0.f;
    float2 acc = make_float2(0.f, 0.f);

    float2 P0, P1;
    {
        int s0 = g_csrc[beg];
        P0 = ((const float2*)(g_xlr2 + (size_t)s0 * 128))[lane];
        if (beg + 1 < end) {
            int s1 = g_csrc[beg + 1];
            P1 = ((const float2*)(g_xlr2 + (size_t)s1 * 128))[lane];
        }
    }

    int k = beg;
    while (k + 1 < end) {
        float2 c = P0, d = P1;
        if (k + 2 < end) {
            int s = g_csrc[k + 2];
            P0 = ((const float2*)(g_xlr2 + (size_t)s * 128))[lane];
        }
        if (k + 3 < end) {
            int s = g_csrc[k + 3];
            P1 = ((const float2*)(g_xlr2 + (size_t)s * 128))[lane];
        }
        float p = lrelu(c.x + b.x) * w.x + lrelu(c.y + b.y) * w.y;
        float q = lrelu(d.x + b.x) * w.x + lrelu(d.y + b.y) * w.y;
#pragma unroll
        for (int o = 16; o > 0; o >>= 1) {
            p += __shfl_xor_sync(0xffffffffu, p, o);
            q += __shfl_xor_sync(0xffffffffu, q, o);
        }
        float mn = fmaxf(m, fmaxf(p, q));
        float sc = __expf(m - mn);
        float wp = __expf(p - mn);
        float wq = __expf(q - mn);
        den = den * sc + wp + wq;
        acc.x = acc.x * sc + wp * c.x + wq * d.x;
        acc.y = acc.y * sc + wp * c.y + wq * d.y;
        m = mn;
        k += 2;
    }
    if (k < end) {
        float2 c = P0;
        float p = lrelu(c.x + b.x) * w.x + lrelu(c.y + b.y) * w.y;
#pragma unroll
        for (int o = 16; o > 0; o >>= 1) p += __shfl_xor_sync(0xffffffffu, p, o);
        float mn = fmaxf(m, p);
        float sc = __expf(m - mn);
        float wp = __expf(p - mn);
        den = den * sc + wp;
        acc.x = acc.x * sc + wp * c.x;
        acc.y = acc.y * sc + wp * c.y;
        m = mn;
    }

    float r = 1.f / (den + 1e-16f);
    float2 bv = ((const float2*)bias)[lane];
    float vx = acc.x * r + bv.x;
    float vy = acc.y * r + bv.y;

    float ssum = vx + vy;
#pragma unroll
    for (int o = 16; o > 0; o >>= 1) ssum += __shfl_xor_sync(0xffffffffu, ssum, o);
    float mu = ssum * (1.f / 64.f);
    float dx = vx - mu, dy = vy - mu;
    float sq = dx * dx + dy * dy;
#pragma unroll
    for (int o = 16; o > 0; o >>= 1) sq += __shfl_xor_sync(0xffffffffu, sq, o);
    float inv = rsqrtf(sq * (1.f / 64.f) + 1e-5f);

    float2 gv = ((const float2*)lng)[lane];
    float2 b2 = ((const float2*)lnb)[lane];
    float2 o;
    o.x = dx * inv * gv.x + b2.x;
    o.y = dy * inv * gv.y + b2.y;
    ((float2*)(out + (size_t)n * HID))[lane] = o;
}

// ---------------- launch ----------------
extern "C" void kernel_launch(void* const* d_in, const int* in_sizes, int n_in,
                              void* d_out, int out_size) {
    const float* x    = (const float*)d_in[0];
    const int*   ei   = (const int*)d_in[1];
    const float* W1l  = (const float*)d_in[2];
    const float* W1r  = (const float*)d_in[3];
    const float* att1 = (const float*)d_in[4];
    const float* b1   = (const float*)d_in[5];
    const float* ln1g = (const float*)d_in[6];
    const float* ln1b = (const float*)d_in[7];
    const float* W2l  = (const float*)d_in[8];
    const float* W2r  = (const float*)d_in[9];
    const float* att2 = (const float*)d_in[10];
    const float* b2   = (const float*)d_in[11];
    const float* ln2g = (const float*)d_in[12];
    const float* ln2b = (const float*)d_in[13];
    float* out = (float*)d_out;

    const int* srcp = ei;
    const int* dstp = ei + Ein;

    float *hp, *w2p, *xlr2p;
    cudaGetSymbolAddress((void**)&hp,    g_h);
    cudaGetSymbolAddress((void**)&w2p,   g_w2);
    cudaGetSymbolAddress((void**)&xlr2p, g_xlr2);

    const int T = 256;

    // fork: CSR build on side stream, concurrent with conv + gemm1
    cudaStream_t s2;
    cudaStreamCreateWithFlags(&s2, cudaStreamNonBlocking);
    cudaEvent_t evF, evJ;
    cudaEventCreateWithFlags(&evF, cudaEventDisableTiming);
    cudaEventCreateWithFlags(&evJ, cudaEventDisableTiming);
    cudaEventRecord(evF, 0);
    cudaStreamWaitEvent(s2, evF, 0);

    k_zero<<<(Nn + T - 1) / T, T, 0, s2>>>();
    k_hist<<<(ET + T - 1) / T, T, 0, s2>>>(dstp);
    k_scan<<<1, 1024, 0, s2>>>();
    k_fill<<<(ET + T - 1) / T, T, 0, s2>>>(srcp, dstp);
    cudaEventRecord(evJ, s2);

    // main stream: conversions + layer1 GEMM
    k_convw<<<(NT * FIN + T - 1) / T, T>>>(W1l, W1r);
    k_convx<<<(Nn * FIN + T - 1) / T, T>>>(x);
    k_packw2<<<(64 * 128 + T - 1) / T, T>>>(W2l, W2r);

    size_t smbytes = SM_ELEMS * sizeof(__half);   // 55296
    cudaFuncSetAttribute(k_gemm1, cudaFuncAttributeMaxDynamicSharedMemorySize, (int)smbytes);
    dim3 gg(NT / 128, (Nn + 127) / 128);
    k_gemm1<<<gg, 256, smbytes>>>();

    // join CSR before the gather phase
    cudaStreamWaitEvent(0, evJ, 0);

    // layer1 fused attention + LN + relu
    k_gat1<<<(Nn * 32 + T - 1) / T, T>>>(att1, b1, ln1g, ln1b);

    // layer2 GEMM: [50000,64] @ [64,128] (fp32, fused l|r)
    dim3 g2(2, (Nn + 127) / 128), blk(16, 16);
    sgemm<<<g2, blk>>>(hp, w2p, xlr2p, Nn, HID, 128);

    // layer2 fused attention + LN -> out
    k_gat2<<<(Nn * 32 + T - 1) / T, T>>>(att2, b2, ln2g, ln2b, out);
}

// round 13
// speedup vs baseline: 3.2015x; 1.1043x over previous
#include <cuda_runtime.h>
#include <cuda_fp16.h>
#include <math.h>
#include <stdint.h>

#define Nn  50000
#define Ein 800000
#define ET  850000      // Ein + Nn self loops
#define FIN 256
#define HID 64
#define H1  4
#define NT  512         // xl (256) ++ xr (256)

// ---------------- scratch (device globals; no allocation allowed) ----------
__device__ __align__(16) __half g_x1h[(size_t)Nn * NT];   // layer1 proj fp16 [xl|xr]
__device__ __align__(16) __half g_x2h[(size_t)Nn * 128];  // layer2 proj fp16 [xl2|xr2]
__device__ __align__(16) __half g_xh [Nn * FIN];          // x rounded to fp16
__device__ __align__(16) __half g_whi[NT * FIN];          // Wt[n][k] fp16 hi
__device__ __align__(16) __half g_wlo[NT * FIN];          // Wt[n][k] fp16 lo
__device__ float g_h[Nn * HID];
__device__ float g_w2[64 * 128];            // packed [W2l | W2r], B[k][n]

__device__ int g_deg[Nn];
__device__ int g_cur[Nn];
__device__ int g_off[Nn + 1];
__device__ int g_csrc[ET];

__device__ __forceinline__ float lrelu(float z) {
    return fmaxf(z, 0.f) + 0.2f * fminf(z, 0.f);
}

__device__ __forceinline__ void h8tof(uint4 v, float* f) {
    const __half2* h = (const __half2*)&v;
#pragma unroll
    for (int j = 0; j < 4; j++) {
        float2 t = __half22float2(h[j]);
        f[2 * j] = t.x; f[2 * j + 1] = t.y;
    }
}

// ---------------- CSR build ----------------
__global__ void k_zero() {
    int i = blockIdx.x * blockDim.x + threadIdx.x;
    if (i < Nn) { g_deg[i] = 0; g_cur[i] = 0; }
}

__global__ void k_hist(const int* __restrict__ dst) {
    int e = blockIdx.x * blockDim.x + threadIdx.x;
    if (e >= ET) return;
    int d = (e < Ein) ? dst[e] : (e - Ein);
    atomicAdd(&g_deg[d], 1);
}

__global__ void k_scan() {   // single block, 1024 threads, 4 elems/thread
    __shared__ int wsum[32];
    __shared__ int carry_s;
    int t = threadIdx.x;
    if (t == 0) carry_s = 0;
    __syncthreads();
    for (int base = 0; base < Nn; base += 4096) {
        int i0 = base + t * 4;
        int v0 = (i0 + 0 < Nn) ? g_deg[i0 + 0] : 0;
        int v1 = (i0 + 1 < Nn) ? g_deg[i0 + 1] : 0;
        int v2 = (i0 + 2 < Nn) ? g_deg[i0 + 2] : 0;
        int v3 = (i0 + 3 < Nn) ? g_deg[i0 + 3] : 0;
        int tsum = v0 + v1 + v2 + v3;
        int x = tsum;
#pragma unroll
        for (int o = 1; o < 32; o <<= 1) {
            int y = __shfl_up_sync(0xffffffffu, x, o);
            if ((t & 31) >= o) x += y;
        }
        if ((t & 31) == 31) wsum[t >> 5] = x;
        __syncthreads();
        if (t < 32) {
            int wv = wsum[t];
#pragma unroll
            for (int o = 1; o < 32; o <<= 1) {
                int y = __shfl_up_sync(0xffffffffu, wv, o);
                if (t >= o) wv += y;
            }
            wsum[t] = wv;
        }
        __syncthreads();
        int excl = x - tsum + ((t >> 5) ? wsum[(t >> 5) - 1] : 0) + carry_s;
        if (i0 + 0 < Nn) g_off[i0 + 0] = excl;
        if (i0 + 1 < Nn) g_off[i0 + 1] = excl + v0;
        if (i0 + 2 < Nn) g_off[i0 + 2] = excl + v0 + v1;
        if (i0 + 3 < Nn) g_off[i0 + 3] = excl + v0 + v1 + v2;
        int tot = wsum[31];
        __syncthreads();
        if (t == 0) carry_s += tot;
        __syncthreads();
    }
    if (t == 0) g_off[Nn] = carry_s;
}

__global__ void k_fill(const int* __restrict__ src, const int* __restrict__ dst) {
    int e = blockIdx.x * blockDim.x + threadIdx.x;
    if (e >= ET) return;
    int s, d;
    if (e < Ein) { s = src[e]; d = dst[e]; }
    else         { s = e - Ein; d = s; }
    int p = atomicAdd(&g_cur[d], 1);
    g_csrc[g_off[d] + p] = s;
}

// ---------------- conversions ----------------
__global__ void k_convx(const float* __restrict__ x) {
    int i = blockIdx.x * blockDim.x + threadIdx.x;
    if (i >= Nn * FIN) return;
    g_xh[i] = __float2half(x[i]);
}

__global__ void k_convw(const float* __restrict__ Wl, const float* __restrict__ Wr) {
    int i = blockIdx.x * blockDim.x + threadIdx.x;
    if (i >= NT * FIN) return;
    int n = i >> 8, k = i & 255;   // FIN = 256
    float v = (n < 256) ? Wl[k * 256 + n] : Wr[k * 256 + (n - 256)];
    __half hi = __float2half(v);
    g_whi[i] = hi;
    g_wlo[i] = __float2half(v - __half2float(hi));
}

__global__ void k_packw2(const float* __restrict__ Wl, const float* __restrict__ Wr) {
    int i = blockIdx.x * blockDim.x + threadIdx.x;
    if (i >= 64 * 128) return;
    int k = i >> 7, n = i & 127;
    g_w2[i] = (n < 64) ? Wl[k * 64 + n] : Wr[k * 64 + (n - 64)];
}

// ---------------- layer1 GEMM via mma.sync fp16 2-term ----------------
#define TS 72
#define SM_A  0
#define SM_BH (128 * TS)
#define SM_BL (2 * 128 * TS)
#define SM_ELEMS (3 * 128 * TS)

__device__ __forceinline__ void mma16816h(float* c, const uint32_t* a, uint32_t b0, uint32_t b1) {
    asm volatile(
        "mma.sync.aligned.m16n8k16.row.col.f32.f16.f16.f32 "
        "{%0,%1,%2,%3}, {%4,%5,%6,%7}, {%8,%9}, {%0,%1,%2,%3};"
        : "+f"(c[0]), "+f"(c[1]), "+f"(c[2]), "+f"(c[3])
        : "r"(a[0]), "r"(a[1]), "r"(a[2]), "r"(a[3]), "r"(b0), "r"(b1));
}

__global__ void __launch_bounds__(256, 2) k_gemm1() {
    extern __shared__ __half sm[];
    int tid = threadIdx.x;
    int wid = tid >> 5, lane = tid & 31;
    int m0 = blockIdx.y * 128, n0 = blockIdx.x * 128;
    int wm = (wid & 3) * 32, wn = (wid >> 2) * 64;
    int gr = lane >> 2, gc2 = (lane & 3) * 2;

    float acc[2][8][4];
#pragma unroll
    for (int mi = 0; mi < 2; mi++)
#pragma unroll
        for (int f = 0; f < 8; f++)
#pragma unroll
            for (int j = 0; j < 4; j++) acc[mi][f][j] = 0.f;

    for (int kc = 0; kc < 4; kc++) {
        int k0 = kc * 64;
#pragma unroll
        for (int u = tid; u < 1024; u += 256) {
            int r = u >> 3, i = u & 7;
            int m = m0 + r;
            uint4 v = make_uint4(0u, 0u, 0u, 0u);
            if (m < Nn) v = ((const uint4*)(g_xh + (size_t)m * FIN + k0))[i];
            *(uint4*)(sm + SM_A + r * TS + i * 8) = v;
        }
#pragma unroll
        for (int u = tid; u < 1024; u += 256) {
            int r = u >> 3, i = u & 7;
            int n = n0 + r;
            uint4 vh = ((const uint4*)(g_whi + (size_t)n * FIN + k0))[i];
            uint4 vl = ((const uint4*)(g_wlo + (size_t)n * FIN + k0))[i];
            *(uint4*)(sm + SM_BH + r * TS + i * 8) = vh;
            *(uint4*)(sm + SM_BL + r * TS + i * 8) = vl;
        }
        __syncthreads();

#pragma unroll
        for (int kk = 0; kk < 64; kk += 16) {
            uint32_t a[2][4];
#pragma unroll
            for (int mi = 0; mi < 2; mi++) {
                int r0 = wm + mi * 16 + gr;
                a[mi][0] = *(const uint32_t*)(sm + SM_A + (r0)     * TS + kk + gc2);
                a[mi][1] = *(const uint32_t*)(sm + SM_A + (r0 + 8) * TS + kk + gc2);
                a[mi][2] = *(const uint32_t*)(sm + SM_A + (r0)     * TS + kk + gc2 + 8);
                a[mi][3] = *(const uint32_t*)(sm + SM_A + (r0 + 8) * TS + kk + gc2 + 8);
            }
#pragma unroll
            for (int f = 0; f < 8; f++) {
                int nb = wn + f * 8 + gr;
                uint32_t bh0 = *(const uint32_t*)(sm + SM_BH + nb * TS + kk + gc2);
                uint32_t bh1 = *(const uint32_t*)(sm + SM_BH + nb * TS + kk + gc2 + 8);
                uint32_t bl0 = *(const uint32_t*)(sm + SM_BL + nb * TS + kk + gc2);
                uint32_t bl1 = *(const uint32_t*)(sm + SM_BL + nb * TS + kk + gc2 + 8);
#pragma unroll
                for (int mi = 0; mi < 2; mi++) {
                    mma16816h(acc[mi][f], a[mi], bh0, bh1);
                    mma16816h(acc[mi][f], a[mi], bl0, bl1);
                }
            }
        }
        __syncthreads();
    }

#pragma unroll
    for (int mi = 0; mi < 2; mi++) {
        int r0 = m0 + wm + mi * 16 + gr;
#pragma unroll
        for (int f = 0; f < 8; f++) {
            int col = n0 + wn + f * 8 + gc2;
            if (r0 < Nn)
                *(__half2*)(g_x1h + (size_t)r0 * NT + col) =
                    __floats2half2_rn(acc[mi][f][0], acc[mi][f][1]);
            if (r0 + 8 < Nn)
                *(__half2*)(g_x1h + (size_t)(r0 + 8) * NT + col) =
                    __floats2half2_rn(acc[mi][f][2], acc[mi][f][3]);
        }
    }
}

// ---------------- fp32 tiled SGEMM, fp16 output (layer 2) ----------------
__global__ void sgemm_h(const float* __restrict__ A, const float* __restrict__ B,
                        __half* __restrict__ C, int M, int K, int Ncols) {
    const int BM = 128, BK = 16;
    __shared__ float As[BK][BM];
    __shared__ float Bs[BK][64];
    int tx = threadIdx.x, ty = threadIdx.y;
    int tid = ty * 16 + tx;
    int m0 = blockIdx.y * BM, n0 = blockIdx.x * 64;

    float acc[8][4];
#pragma unroll
    for (int r = 0; r < 8; r++)
#pragma unroll
        for (int c = 0; c < 4; c++) acc[r][c] = 0.f;

    for (int k0 = 0; k0 < K; k0 += BK) {
#pragma unroll
        for (int t = 0; t < 2; t++) {
            int i = tid + t * 256;
            int row = i >> 2, kq = i & 3;
            float4 v = make_float4(0.f, 0.f, 0.f, 0.f);
            int m = m0 + row;
            if (m < M) v = *(const float4*)(A + (size_t)m * K + k0 + kq * 4);
            As[kq * 4 + 0][row] = v.x;
            As[kq * 4 + 1][row] = v.y;
            As[kq * 4 + 2][row] = v.z;
            As[kq * 4 + 3][row] = v.w;
        }
        {
            int k = tid >> 4, nq = tid & 15;
            float4 v = *(const float4*)(B + (size_t)(k0 + k) * Ncols + n0 + nq * 4);
            *(float4*)&Bs[k][nq * 4] = v;
        }
        __syncthreads();
#pragma unroll
        for (int kk = 0; kk < BK; kk++) {
            float4 a0 = *(float4*)&As[kk][ty * 8];
            float4 a1 = *(float4*)&As[kk][ty * 8 + 4];
            float4 b  = *(float4*)&Bs[kk][tx * 4];
            float ar[8] = {a0.x, a0.y, a0.z, a0.w, a1.x, a1.y, a1.z, a1.w};
            float br[4] = {b.x, b.y, b.z, b.w};
#pragma unroll
            for (int r = 0; r < 8; r++)
#pragma unroll
                for (int c = 0; c < 4; c++) acc[r][c] = fmaf(ar[r], br[c], acc[r][c]);
        }
        __syncthreads();
    }
#pragma unroll
    for (int r = 0; r < 8; r++) {
        int m = m0 + ty * 8 + r;
        if (m < M) {
            __half2 h0 = __floats2half2_rn(acc[r][0], acc[r][1]);
            __half2 h1 = __floats2half2_rn(acc[r][2], acc[r][3]);
            __half2* o = (__half2*)(C + (size_t)m * Ncols + n0 + tx * 4);
            o[0] = h0; o[1] = h1;
        }
    }
}

// ---------------- layer1 fused attention (fp16 gather, 8ch/lane) ----------
// lane holds channels [8*lane, 8*lane+8); 8-lane group g = lane>>3 owns head g.
__global__ void k_gat1(const float* __restrict__ att, const float* __restrict__ bias,
                       const float* __restrict__ lng, const float* __restrict__ lnb) {
    int n = (blockIdx.x * blockDim.x + threadIdx.x) >> 5;
    int lane = threadIdx.x & 31;
    if (n >= Nn) return;

    float b[8], w[8];
    h8tof(((const uint4*)(g_x1h + (size_t)n * NT + 256))[lane], b);
    {
        const float4* at = (const float4*)(att + 8 * lane);
        float4 t0 = at[0], t1 = at[1];
        w[0] = t0.x; w[1] = t0.y; w[2] = t0.z; w[3] = t0.w;
        w[4] = t1.x; w[5] = t1.y; w[6] = t1.z; w[7] = t1.w;
    }

    int beg = g_off[n], end = g_off[n + 1];
    float m = -1e30f, den = 0.f;
    float acc[8];
#pragma unroll
    for (int j = 0; j < 8; j++) acc[j] = 0.f;

    uint4 P0, P1;
    {
        int s0 = g_csrc[beg];
        P0 = ((const uint4*)(g_x1h + (size_t)s0 * NT))[lane];
        if (beg + 1 < end) {
            int s1 = g_csrc[beg + 1];
            P1 = ((const uint4*)(g_x1h + (size_t)s1 * NT))[lane];
        }
    }

    int k = beg;
    while (k + 1 < end) {
        float c[8], d[8];
        h8tof(P0, c); h8tof(P1, d);
        if (k + 2 < end) {
            int s = g_csrc[k + 2];
            P0 = ((const uint4*)(g_x1h + (size_t)s * NT))[lane];
        }
        if (k + 3 < end) {
            int s = g_csrc[k + 3];
            P1 = ((const uint4*)(g_x1h + (size_t)s * NT))[lane];
        }
        float p = 0.f, q = 0.f;
#pragma unroll
        for (int j = 0; j < 8; j++) {
            p = fmaf(lrelu(c[j] + b[j]), w[j], p);
            q = fmaf(lrelu(d[j] + b[j]), w[j], q);
        }
#pragma unroll
        for (int o = 4; o > 0; o >>= 1) {
            p += __shfl_xor_sync(0xffffffffu, p, o, 8);
            q += __shfl_xor_sync(0xffffffffu, q, o, 8);
        }
        float mn = fmaxf(m, fmaxf(p, q));
        float sc = __expf(m - mn);
        float wp = __expf(p - mn);
        float wq = __expf(q - mn);
        den = den * sc + wp + wq;
#pragma unroll
        for (int j = 0; j < 8; j++) acc[j] = acc[j] * sc + wp * c[j] + wq * d[j];
        m = mn;
        k += 2;
    }
    if (k < end) {
        float c[8];
        h8tof(P0, c);
        float p = 0.f;
#pragma unroll
        for (int j = 0; j < 8; j++) p = fmaf(lrelu(c[j] + b[j]), w[j], p);
#pragma unroll
        for (int o = 4; o > 0; o >>= 1) p += __shfl_xor_sync(0xffffffffu, p, o, 8);
        float mn = fmaxf(m, p);
        float sc = __expf(m - mn);
        float wp = __expf(p - mn);
        den = den * sc + wp;
#pragma unroll
        for (int j = 0; j < 8; j++) acc[j] = acc[j] * sc + wp * c[j];
        m = mn;
    }

    float r = 1.f / (den + 1e-16f);
    int c0 = (lane & 7) * 8;   // base channel slot (0..56)
    float v[8];
#pragma unroll
    for (int j = 0; j < 8; j++) {
        float t = acc[j] * r;
        t += __shfl_xor_sync(0xffffffffu, t, 8);
        t += __shfl_xor_sync(0xffffffffu, t, 16);
        v[j] = 0.25f * t + bias[c0 + j];
    }

    float ssum = 0.f;
#pragma unroll
    for (int j = 0; j < 8; j++) ssum += v[j];
#pragma unroll
    for (int o = 16; o > 0; o >>= 1) ssum += __shfl_xor_sync(0xffffffffu, ssum, o);
    float mu = ssum * (1.f / 256.f);
    float sq = 0.f;
#pragma unroll
    for (int j = 0; j < 8; j++) { v[j] -= mu; sq += v[j] * v[j]; }
#pragma unroll
    for (int o = 16; o > 0; o >>= 1) sq += __shfl_xor_sync(0xffffffffu, sq, o);
    float inv = rsqrtf(sq * (1.f / 256.f) + 1e-5f);

    if (lane < 8) {
        float o0[8];
#pragma unroll
        for (int j = 0; j < 8; j++)
            o0[j] = fmaxf(v[j] * inv * lng[c0 + j] + lnb[c0 + j], 0.f);
        float4* op = (float4*)(g_h + (size_t)n * HID + c0);
        op[0] = make_float4(o0[0], o0[1], o0[2], o0[3]);
        op[1] = make_float4(o0[4], o0[5], o0[6], o0[7]);
    }
}

// ---------------- layer2 fused attention (fp16 gather) ----------------
__global__ void k_gat2(const float* __restrict__ att, const float* __restrict__ bias,
                       const float* __restrict__ lng, const float* __restrict__ lnb,
                       float* __restrict__ out) {
    int n = (blockIdx.x * blockDim.x + threadIdx.x) >> 5;
    int lane = threadIdx.x & 31;
    if (n >= Nn) return;

    float2 b = __half22float2(((const __half2*)(g_x2h + (size_t)n * 128 + 64))[lane]);
    float2 w = ((const float2*)att)[lane];

    int beg = g_off[n], end = g_off[n + 1];
    float m = -1e30f, den = 0.f;
    float2 acc = make_float2(0.f, 0.f);

    __half2 P0, P1;
    {
        int s0 = g_csrc[beg];
        P0 = ((const __half2*)(g_x2h + (size_t)s0 * 128))[lane];
        if (beg + 1 < end) {
            int s1 = g_csrc[beg + 1];
            P1 = ((const __half2*)(g_x2h + (size_t)s1 * 128))[lane];
        }
    }

    int k = beg;
    while (k + 1 < end) {
        float2 c = __half22float2(P0), d = __half22float2(P1);
        if (k + 2 < end) {
            int s = g_csrc[k + 2];
            P0 = ((const __half2*)(g_x2h + (size_t)s * 128))[lane];
        }
        if (k + 3 < end) {
            int s = g_csrc[k + 3];
            P1 = ((const __half2*)(g_x2h + (size_t)s * 128))[lane];
        }
        float p = lrelu(c.x + b.x) * w.x + lrelu(c.y + b.y) * w.y;
        float q = lrelu(d.x + b.x) * w.x + lrelu(d.y + b.y) * w.y;
#pragma unroll
        for (int o = 16; o > 0; o >>= 1) {
            p += __shfl_xor_sync(0xffffffffu, p, o);
            q += __shfl_xor_sync(0xffffffffu, q, o);
        }
        float mn = fmaxf(m, fmaxf(p, q));
        float sc = __expf(m - mn);
        float wp = __expf(p - mn);
        float wq = __expf(q - mn);
        den = den * sc + wp + wq;
        acc.x = acc.x * sc + wp * c.x + wq * d.x;
        acc.y = acc.y * sc + wp * c.y + wq * d.y;
        m = mn;
        k += 2;
    }
    if (k < end) {
        float2 c = __half22float2(P0);
        float p = lrelu(c.x + b.x) * w.x + lrelu(c.y + b.y) * w.y;
#pragma unroll
        for (int o = 16; o > 0; o >>= 1) p += __shfl_xor_sync(0xffffffffu, p, o);
        float mn = fmaxf(m, p);
        float sc = __expf(m - mn);
        float wp = __expf(p - mn);
        den = den * sc + wp;
        acc.x = acc.x * sc + wp * c.x;
        acc.y = acc.y * sc + wp * c.y;
        m = mn;
    }

    float r = 1.f / (den + 1e-16f);
    float2 bv = ((const float2*)bias)[lane];
    float vx = acc.x * r + bv.x;
    float vy = acc.y * r + bv.y;

    float ssum = vx + vy;
#pragma unroll
    for (int o = 16; o > 0; o >>= 1) ssum += __shfl_xor_sync(0xffffffffu, ssum, o);
    float mu = ssum * (1.f / 64.f);
    float dx = vx - mu, dy = vy - mu;
    float sq = dx * dx + dy * dy;
#pragma unroll
    for (int o = 16; o > 0; o >>= 1) sq += __shfl_xor_sync(0xffffffffu, sq, o);
    float inv = rsqrtf(sq * (1.f / 64.f) + 1e-5f);

    float2 gv = ((const float2*)lng)[lane];
    float2 b2 = ((const float2*)lnb)[lane];
    float2 o;
    o.x = dx * inv * gv.x + b2.x;
    o.y = dy * inv * gv.y + b2.y;
    ((float2*)(out + (size_t)n * HID))[lane] = o;
}

// ---------------- launch ----------------
extern "C" void kernel_launch(void* const* d_in, const int* in_sizes, int n_in,
                              void* d_out, int out_size) {
    const float* x    = (const float*)d_in[0];
    const int*   ei   = (const int*)d_in[1];
    const float* W1l  = (const float*)d_in[2];
    const float* W1r  = (const float*)d_in[3];
    const float* att1 = (const float*)d_in[4];
    const float* b1   = (const float*)d_in[5];
    const float* ln1g = (const float*)d_in[6];
    const float* ln1b = (const float*)d_in[7];
    const float* W2l  = (const float*)d_in[8];
    const float* W2r  = (const float*)d_in[9];
    const float* att2 = (const float*)d_in[10];
    const float* b2   = (const float*)d_in[11];
    const float* ln2g = (const float*)d_in[12];
    const float* ln2b = (const float*)d_in[13];
    float* out = (float*)d_out;

    const int* srcp = ei;
    const int* dstp = ei + Ein;

    float *hp, *w2p;
    __half* x2hp;
    cudaGetSymbolAddress((void**)&hp,   g_h);
    cudaGetSymbolAddress((void**)&w2p,  g_w2);
    cudaGetSymbolAddress((void**)&x2hp, g_x2h);

    const int T = 256;

    // fork: CSR build on side stream, concurrent with conv + gemm1
    cudaStream_t s2;
    cudaStreamCreateWithFlags(&s2, cudaStreamNonBlocking);
    cudaEvent_t evF, evJ;
    cudaEventCreateWithFlags(&evF, cudaEventDisableTiming);
    cudaEventCreateWithFlags(&evJ, cudaEventDisableTiming);
    cudaEventRecord(evF, 0);
    cudaStreamWaitEvent(s2, evF, 0);

    k_zero<<<(Nn + T - 1) / T, T, 0, s2>>>();
    k_hist<<<(ET + T - 1) / T, T, 0, s2>>>(dstp);
    k_scan<<<1, 1024, 0, s2>>>();
    k_fill<<<(ET + T - 1) / T, T, 0, s2>>>(srcp, dstp);
    cudaEventRecord(evJ, s2);

    // main stream: conversions + layer1 GEMM
    k_convw<<<(NT * FIN + T - 1) / T, T>>>(W1l, W1r);
    k_convx<<<(Nn * FIN + T - 1) / T, T>>>(x);
    k_packw2<<<(64 * 128 + T - 1) / T, T>>>(W2l, W2r);

    size_t smbytes = SM_ELEMS * sizeof(__half);   // 55296
    cudaFuncSetAttribute(k_gemm1, cudaFuncAttributeMaxDynamicSharedMemorySize, (int)smbytes);
    dim3 gg(NT / 128, (Nn + 127) / 128);
    k_gemm1<<<gg, 256, smbytes>>>();

    // join CSR before the gather phase
    cudaStreamWaitEvent(0, evJ, 0);

    // layer1 fused attention + LN + relu
    k_gat1<<<(Nn * 32 + T - 1) / T, T>>>(att1, b1, ln1g, ln1b);

    // layer2 GEMM: [50000,64] @ [64,128] (fp32 math, fp16 store)
    dim3 g2(2, (Nn + 127) / 128), blk(16, 16);
    sgemm_h<<<g2, blk>>>(hp, w2p, x2hp, Nn, HID, 128);

    // layer2 fused attention + LN -> out
    k_gat2<<<(Nn * 32 + T - 1) / T, T>>>(att2, b2, ln2g, ln2b, out);
}

// round 14
// speedup vs baseline: 3.4765x; 1.0859x over previous
#include <cuda_runtime.h>
#include <cuda_fp16.h>
#include <math.h>
#include <stdint.h>

#define Nn  50000
#define Ein 800000
#define ET  850000      // Ein + Nn self loops
#define FIN 256
#define HID 64
#define H1  4
#define NT  512         // xl (256) ++ xr (256)

// ---------------- scratch (device globals; no allocation allowed) ----------
__device__ __align__(16) __half g_x1h[(size_t)Nn * NT];   // layer1 proj fp16 [xl|xr]
__device__ __align__(16) __half g_x2h[(size_t)Nn * 128];  // layer2 proj fp16 [xl2|xr2]
__device__ __align__(16) __half g_xh [Nn * FIN];          // x rounded to fp16
__device__ __align__(16) __half g_whi[NT * FIN];          // W1t[n][k] fp16 hi
__device__ __align__(16) __half g_wlo[NT * FIN];          // W1t[n][k] fp16 lo
__device__ __align__(16) __half g_hh [Nn * HID];          // layer1 output h, fp16
__device__ __align__(16) __half g_w2hi[128 * 64];         // W2t[n][k] fp16 hi
__device__ __align__(16) __half g_w2lo[128 * 64];         // W2t[n][k] fp16 lo

__device__ int g_deg[Nn];
__device__ int g_cur[Nn];
__device__ int g_off[Nn + 1];
__device__ int g_csrc[ET];

__device__ __forceinline__ float lrelu(float z) {
    return fmaxf(z, 0.f) + 0.2f * fminf(z, 0.f);
}

__device__ __forceinline__ void h8tof(uint4 v, float* f) {
    const __half2* h = (const __half2*)&v;
#pragma unroll
    for (int j = 0; j < 4; j++) {
        float2 t = __half22float2(h[j]);
        f[2 * j] = t.x; f[2 * j + 1] = t.y;
    }
}

// ---------------- CSR build ----------------
__global__ void k_zero() {
    int i = blockIdx.x * blockDim.x + threadIdx.x;
    if (i < Nn) { g_deg[i] = 0; g_cur[i] = 0; }
}

__global__ void k_hist(const int* __restrict__ dst) {
    int e = blockIdx.x * blockDim.x + threadIdx.x;
    if (e >= ET) return;
    int d = (e < Ein) ? dst[e] : (e - Ein);
    atomicAdd(&g_deg[d], 1);
}

__global__ void k_scan() {   // single block, 1024 threads, 4 elems/thread
    __shared__ int wsum[32];
    __shared__ int carry_s;
    int t = threadIdx.x;
    if (t == 0) carry_s = 0;
    __syncthreads();
    for (int base = 0; base < Nn; base += 4096) {
        int i0 = base + t * 4;
        int v0 = (i0 + 0 < Nn) ? g_deg[i0 + 0] : 0;
        int v1 = (i0 + 1 < Nn) ? g_deg[i0 + 1] : 0;
        int v2 = (i0 + 2 < Nn) ? g_deg[i0 + 2] : 0;
        int v3 = (i0 + 3 < Nn) ? g_deg[i0 + 3] : 0;
        int tsum = v0 + v1 + v2 + v3;
        int x = tsum;
#pragma unroll
        for (int o = 1; o < 32; o <<= 1) {
            int y = __shfl_up_sync(0xffffffffu, x, o);
            if ((t & 31) >= o) x += y;
        }
        if ((t & 31) == 31) wsum[t >> 5] = x;
        __syncthreads();
        if (t < 32) {
            int wv = wsum[t];
#pragma unroll
            for (int o = 1; o < 32; o <<= 1) {
                int y = __shfl_up_sync(0xffffffffu, wv, o);
                if (t >= o) wv += y;
            }
            wsum[t] = wv;
        }
        __syncthreads();
        int excl = x - tsum + ((t >> 5) ? wsum[(t >> 5) - 1] : 0) + carry_s;
        if (i0 + 0 < Nn) g_off[i0 + 0] = excl;
        if (i0 + 1 < Nn) g_off[i0 + 1] = excl + v0;
        if (i0 + 2 < Nn) g_off[i0 + 2] = excl + v0 + v1;
        if (i0 + 3 < Nn) g_off[i0 + 3] = excl + v0 + v1 + v2;
        int tot = wsum[31];
        __syncthreads();
        if (t == 0) carry_s += tot;
        __syncthreads();
    }
    if (t == 0) g_off[Nn] = carry_s;
}

__global__ void k_fill(const int* __restrict__ src, const int* __restrict__ dst) {
    int e = blockIdx.x * blockDim.x + threadIdx.x;
    if (e >= ET) return;
    int s, d;
    if (e < Ein) { s = src[e]; d = dst[e]; }
    else         { s = e - Ein; d = s; }
    int p = atomicAdd(&g_cur[d], 1);
    g_csrc[g_off[d] + p] = s;
}

// ---------------- conversions ----------------
__global__ void k_convx(const float* __restrict__ x) {
    int i = blockIdx.x * blockDim.x + threadIdx.x;
    if (i >= Nn * FIN) return;
    g_xh[i] = __float2half(x[i]);
}

__global__ void k_convw(const float* __restrict__ Wl, const float* __restrict__ Wr) {
    int i = blockIdx.x * blockDim.x + threadIdx.x;
    if (i >= NT * FIN) return;
    int n = i >> 8, k = i & 255;   // FIN = 256
    float v = (n < 256) ? Wl[k * 256 + n] : Wr[k * 256 + (n - 256)];
    __half hi = __float2half(v);
    g_whi[i] = hi;
    g_wlo[i] = __float2half(v - __half2float(hi));
}

__global__ void k_convw2(const float* __restrict__ Wl, const float* __restrict__ Wr) {
    int i = blockIdx.x * blockDim.x + threadIdx.x;
    if (i >= 128 * 64) return;
    int n = i >> 6, k = i & 63;
    float v = (n < 64) ? Wl[k * 64 + n] : Wr[k * 64 + (n - 64)];
    __half hi = __float2half(v);
    g_w2hi[i] = hi;
    g_w2lo[i] = __float2half(v - __half2float(hi));
}

// ---------------- layer1 GEMM via mma.sync fp16 2-term ----------------
#define TS 72
#define SM_A  0
#define SM_BH (128 * TS)
#define SM_BL (2 * 128 * TS)
#define SM_ELEMS (3 * 128 * TS)

__device__ __forceinline__ void mma16816h(float* c, const uint32_t* a, uint32_t b0, uint32_t b1) {
    asm volatile(
        "mma.sync.aligned.m16n8k16.row.col.f32.f16.f16.f32 "
        "{%0,%1,%2,%3}, {%4,%5,%6,%7}, {%8,%9}, {%0,%1,%2,%3};"
        : "+f"(c[0]), "+f"(c[1]), "+f"(c[2]), "+f"(c[3])
        : "r"(a[0]), "r"(a[1]), "r"(a[2]), "r"(a[3]), "r"(b0), "r"(b1));
}

__global__ void __launch_bounds__(256, 2) k_gemm1() {
    extern __shared__ __half sm[];
    int tid = threadIdx.x;
    int wid = tid >> 5, lane = tid & 31;
    int m0 = blockIdx.y * 128, n0 = blockIdx.x * 128;
    int wm = (wid & 3) * 32, wn = (wid >> 2) * 64;
    int gr = lane >> 2, gc2 = (lane & 3) * 2;

    float acc[2][8][4];
#pragma unroll
    for (int mi = 0; mi < 2; mi++)
#pragma unroll
        for (int f = 0; f < 8; f++)
#pragma unroll
            for (int j = 0; j < 4; j++) acc[mi][f][j] = 0.f;

    for (int kc = 0; kc < 4; kc++) {
        int k0 = kc * 64;
#pragma unroll
        for (int u = tid; u < 1024; u += 256) {
            int r = u >> 3, i = u & 7;
            int m = m0 + r;
            uint4 v = make_uint4(0u, 0u, 0u, 0u);
            if (m < Nn) v = ((const uint4*)(g_xh + (size_t)m * FIN + k0))[i];
            *(uint4*)(sm + SM_A + r * TS + i * 8) = v;
        }
#pragma unroll
        for (int u = tid; u < 1024; u += 256) {
            int r = u >> 3, i = u & 7;
            int n = n0 + r;
            uint4 vh = ((const uint4*)(g_whi + (size_t)n * FIN + k0))[i];
            uint4 vl = ((const uint4*)(g_wlo + (size_t)n * FIN + k0))[i];
            *(uint4*)(sm + SM_BH + r * TS + i * 8) = vh;
            *(uint4*)(sm + SM_BL + r * TS + i * 8) = vl;
        }
        __syncthreads();

#pragma unroll
        for (int kk = 0; kk < 64; kk += 16) {
            uint32_t a[2][4];
#pragma unroll
            for (int mi = 0; mi < 2; mi++) {
                int r0 = wm + mi * 16 + gr;
                a[mi][0] = *(const uint32_t*)(sm + SM_A + (r0)     * TS + kk + gc2);
                a[mi][1] = *(const uint32_t*)(sm + SM_A + (r0 + 8) * TS + kk + gc2);
                a[mi][2] = *(const uint32_t*)(sm + SM_A + (r0)     * TS + kk + gc2 + 8);
                a[mi][3] = *(const uint32_t*)(sm + SM_A + (r0 + 8) * TS + kk + gc2 + 8);
            }
#pragma unroll
            for (int f = 0; f < 8; f++) {
                int nb = wn + f * 8 + gr;
                uint32_t bh0 = *(const uint32_t*)(sm + SM_BH + nb * TS + kk + gc2);
                uint32_t bh1 = *(const uint32_t*)(sm + SM_BH + nb * TS + kk + gc2 + 8);
                uint32_t bl0 = *(const uint32_t*)(sm + SM_BL + nb * TS + kk + gc2);
                uint32_t bl1 = *(const uint32_t*)(sm + SM_BL + nb * TS + kk + gc2 + 8);
#pragma unroll
                for (int mi = 0; mi < 2; mi++) {
                    mma16816h(acc[mi][f], a[mi], bh0, bh1);
                    mma16816h(acc[mi][f], a[mi], bl0, bl1);
                }
            }
        }
        __syncthreads();
    }

#pragma unroll
    for (int mi = 0; mi < 2; mi++) {
        int r0 = m0 + wm + mi * 16 + gr;
#pragma unroll
        for (int f = 0; f < 8; f++) {
            int col = n0 + wn + f * 8 + gc2;
            if (r0 < Nn)
                *(__half2*)(g_x1h + (size_t)r0 * NT + col) =
                    __floats2half2_rn(acc[mi][f][0], acc[mi][f][1]);
            if (r0 + 8 < Nn)
                *(__half2*)(g_x1h + (size_t)(r0 + 8) * NT + col) =
                    __floats2half2_rn(acc[mi][f][2], acc[mi][f][3]);
        }
    }
}

// ---------------- layer2 GEMM via mma.sync fp16 2-term (K=64, N=128) ------
__global__ void __launch_bounds__(256, 2) k_gemm2() {
    extern __shared__ __half sm[];
    int tid = threadIdx.x;
    int wid = tid >> 5, lane = tid & 31;
    int m0 = blockIdx.x * 128;
    int wm = (wid & 3) * 32, wn = (wid >> 2) * 64;
    int gr = lane >> 2, gc2 = (lane & 3) * 2;

    float acc[2][8][4];
#pragma unroll
    for (int mi = 0; mi < 2; mi++)
#pragma unroll
        for (int f = 0; f < 8; f++)
#pragma unroll
            for (int j = 0; j < 4; j++) acc[mi][f][j] = 0.f;

    // A: 128 rows x 64 halfs from g_hh
#pragma unroll
    for (int u = tid; u < 1024; u += 256) {
        int r = u >> 3, i = u & 7;
        int m = m0 + r;
        uint4 v = make_uint4(0u, 0u, 0u, 0u);
        if (m < Nn) v = ((const uint4*)(g_hh + (size_t)m * HID))[i];
        *(uint4*)(sm + SM_A + r * TS + i * 8) = v;
    }
    // B: 128 n-rows x 64 halfs, hi + lo
#pragma unroll
    for (int u = tid; u < 1024; u += 256) {
        int r = u >> 3, i = u & 7;
        uint4 vh = ((const uint4*)(g_w2hi + r * 64))[i];
        uint4 vl = ((const uint4*)(g_w2lo + r * 64))[i];
        *(uint4*)(sm + SM_BH + r * TS + i * 8) = vh;
        *(uint4*)(sm + SM_BL + r * TS + i * 8) = vl;
    }
    __syncthreads();

#pragma unroll
    for (int kk = 0; kk < 64; kk += 16) {
        uint32_t a[2][4];
#pragma unroll
        for (int mi = 0; mi < 2; mi++) {
            int r0 = wm + mi * 16 + gr;
            a[mi][0] = *(const uint32_t*)(sm + SM_A + (r0)     * TS + kk + gc2);
            a[mi][1] = *(const uint32_t*)(sm + SM_A + (r0 + 8) * TS + kk + gc2);
            a[mi][2] = *(const uint32_t*)(sm + SM_A + (r0)     * TS + kk + gc2 + 8);
            a[mi][3] = *(const uint32_t*)(sm + SM_A + (r0 + 8) * TS + kk + gc2 + 8);
        }
#pragma unroll
        for (int f = 0; f < 8; f++) {
            int nb = wn + f * 8 + gr;
            uint32_t bh0 = *(const uint32_t*)(sm + SM_BH + nb * TS + kk + gc2);
            uint32_t bh1 = *(const uint32_t*)(sm + SM_BH + nb * TS + kk + gc2 + 8);
            uint32_t bl0 = *(const uint32_t*)(sm + SM_BL + nb * TS + kk + gc2);
            uint32_t bl1 = *(const uint32_t*)(sm + SM_BL + nb * TS + kk + gc2 + 8);
#pragma unroll
            for (int mi = 0; mi < 2; mi++) {
                mma16816h(acc[mi][f], a[mi], bh0, bh1);
                mma16816h(acc[mi][f], a[mi], bl0, bl1);
            }
        }
    }

#pragma unroll
    for (int mi = 0; mi < 2; mi++) {
        int r0 = m0 + wm + mi * 16 + gr;
#pragma unroll
        for (int f = 0; f < 8; f++) {
            int col = wn + f * 8 + gc2;
            if (r0 < Nn)
                *(__half2*)(g_x2h + (size_t)r0 * 128 + col) =
                    __floats2half2_rn(acc[mi][f][0], acc[mi][f][1]);
            if (r0 + 8 < Nn)
                *(__half2*)(g_x2h + (size_t)(r0 + 8) * 128 + col) =
                    __floats2half2_rn(acc[mi][f][2], acc[mi][f][3]);
        }
    }
}

// ---------------- layer1 fused attention (no-max softmax, fp16 gather) ----
// lane holds channels [8*lane, 8*lane+8); 8-lane group g = lane>>3 owns head g.
__global__ void k_gat1(const float* __restrict__ att, const float* __restrict__ bias,
                       const float* __restrict__ lng, const float* __restrict__ lnb) {
    int n = (blockIdx.x * blockDim.x + threadIdx.x) >> 5;
    int lane = threadIdx.x & 31;
    if (n >= Nn) return;

    float b[8], w[8];
    h8tof(((const uint4*)(g_x1h + (size_t)n * NT + 256))[lane], b);
    {
        const float4* at = (const float4*)(att + 8 * lane);
        float4 t0 = at[0], t1 = at[1];
        w[0] = t0.x; w[1] = t0.y; w[2] = t0.z; w[3] = t0.w;
        w[4] = t1.x; w[5] = t1.y; w[6] = t1.z; w[7] = t1.w;
    }

    int beg = g_off[n], end = g_off[n + 1];
    float den = 0.f;
    float acc[8];
#pragma unroll
    for (int j = 0; j < 8; j++) acc[j] = 0.f;

    uint4 P0, P1;
    {
        int s0 = g_csrc[beg];
        P0 = ((const uint4*)(g_x1h + (size_t)s0 * NT))[lane];
        if (beg + 1 < end) {
            int s1 = g_csrc[beg + 1];
            P1 = ((const uint4*)(g_x1h + (size_t)s1 * NT))[lane];
        }
    }

    int k = beg;
    while (k + 1 < end) {
        float c[8], d[8];
        h8tof(P0, c); h8tof(P1, d);
        if (k + 2 < end) {
            int s = g_csrc[k + 2];
            P0 = ((const uint4*)(g_x1h + (size_t)s * NT))[lane];
        }
        if (k + 3 < end) {
            int s = g_csrc[k + 3];
            P1 = ((const uint4*)(g_x1h + (size_t)s * NT))[lane];
        }
        float p = 0.f, q = 0.f;
#pragma unroll
        for (int j = 0; j < 8; j++) {
            p = fmaf(lrelu(c[j] + b[j]), w[j], p);
            q = fmaf(lrelu(d[j] + b[j]), w[j], q);
        }
#pragma unroll
        for (int o = 4; o > 0; o >>= 1) {
            p += __shfl_xor_sync(0xffffffffu, p, o, 8);
            q += __shfl_xor_sync(0xffffffffu, q, o, 8);
        }
        float wp = __expf(p);
        float wq = __expf(q);
        den += wp + wq;
#pragma unroll
        for (int j = 0; j < 8; j++) acc[j] = fmaf(wp, c[j], fmaf(wq, d[j], acc[j]));
        k += 2;
    }
    if (k < end) {
        float c[8];
        h8tof(P0, c);
        float p = 0.f;
#pragma unroll
        for (int j = 0; j < 8; j++) p = fmaf(lrelu(c[j] + b[j]), w[j], p);
#pragma unroll
        for (int o = 4; o > 0; o >>= 1) p += __shfl_xor_sync(0xffffffffu, p, o, 8);
        float wp = __expf(p);
        den += wp;
#pragma unroll
        for (int j = 0; j < 8; j++) acc[j] = fmaf(wp, c[j], acc[j]);
    }

    float r = 1.f / (den + 1e-16f);
    int c0 = (lane & 7) * 8;   // base channel slot (0..56)
    float v[8];
#pragma unroll
    for (int j = 0; j < 8; j++) {
        float t = acc[j] * r;
        t += __shfl_xor_sync(0xffffffffu, t, 8);
        t += __shfl_xor_sync(0xffffffffu, t, 16);
        v[j] = 0.25f * t + bias[c0 + j];
    }

    float ssum = 0.f;
#pragma unroll
    for (int j = 0; j < 8; j++) ssum += v[j];
#pragma unroll
    for (int o = 16; o > 0; o >>= 1) ssum += __shfl_xor_sync(0xffffffffu, ssum, o);
    float mu = ssum * (1.f / 256.f);
    float sq = 0.f;
#pragma unroll
    for (int j = 0; j < 8; j++) { v[j] -= mu; sq += v[j] * v[j]; }
#pragma unroll
    for (int o = 16; o > 0; o >>= 1) sq += __shfl_xor_sync(0xffffffffu, sq, o);
    float inv = rsqrtf(sq * (1.f / 256.f) + 1e-5f);

    if (lane < 8) {
        __half hv[8];
#pragma unroll
        for (int j = 0; j < 8; j++)
            hv[j] = __float2half(fmaxf(v[j] * inv * lng[c0 + j] + lnb[c0 + j], 0.f));
        *(uint4*)(g_hh + (size_t)n * HID + c0) = *(uint4*)hv;
    }
}

// ---------------- layer2 fused attention (no-max softmax, fp16 gather) ----
__global__ void k_gat2(const float* __restrict__ att, const float* __restrict__ bias,
                       const float* __restrict__ lng, const float* __restrict__ lnb,
                       float* __restrict__ out) {
    int n = (blockIdx.x * blockDim.x + threadIdx.x) >> 5;
    int lane = threadIdx.x & 31;
    if (n >= Nn) return;

    float2 b = __half22float2(((const __half2*)(g_x2h + (size_t)n * 128 + 64))[lane]);
    float2 w = ((const float2*)att)[lane];

    int beg = g_off[n], end = g_off[n + 1];
    float den = 0.f;
    float2 acc = make_float2(0.f, 0.f);

    __half2 P0, P1;
    {
        int s0 = g_csrc[beg];
        P0 = ((const __half2*)(g_x2h + (size_t)s0 * 128))[lane];
        if (beg + 1 < end) {
            int s1 = g_csrc[beg + 1];
            P1 = ((const __half2*)(g_x2h + (size_t)s1 * 128))[lane];
        }
    }

    int k = beg;
    while (k + 1 < end) {
        float2 c = __half22float2(P0), d = __half22float2(P1);
        if (k + 2 < end) {
            int s = g_csrc[k + 2];
            P0 = ((const __half2*)(g_x2h + (size_t)s * 128))[lane];
        }
        if (k + 3 < end) {
            int s = g_csrc[k + 3];
            P1 = ((const __half2*)(g_x2h + (size_t)s * 128))[lane];
        }
        float p = lrelu(c.x + b.x) * w.x + lrelu(c.y + b.y) * w.y;
        float q = lrelu(d.x + b.x) * w.x + lrelu(d.y + b.y) * w.y;
#pragma unroll
        for (int o = 16; o > 0; o >>= 1) {
            p += __shfl_xor_sync(0xffffffffu, p, o);
            q += __shfl_xor_sync(0xffffffffu, q, o);
        }
        float wp = __expf(p);
        float wq = __expf(q);
        den += wp + wq;
        acc.x = fmaf(wp, c.x, fmaf(wq, d.x, acc.x));
        acc.y = fmaf(wp, c.y, fmaf(wq, d.y, acc.y));
        k += 2;
    }
    if (k < end) {
        float2 c = __half22float2(P0);
        float p = lrelu(c.x + b.x) * w.x + lrelu(c.y + b.y) * w.y;
#pragma unroll
        for (int o = 16; o > 0; o >>= 1) p += __shfl_xor_sync(0xffffffffu, p, o);
        float wp = __expf(p);
        den += wp;
        acc.x = fmaf(wp, c.x, acc.x);
        acc.y = fmaf(wp, c.y, acc.y);
    }

    float r = 1.f / (den + 1e-16f);
    float2 bv = ((const float2*)bias)[lane];
    float vx = acc.x * r + bv.x;
    float vy = acc.y * r + bv.y;

    float ssum = vx + vy;
#pragma unroll
    for (int o = 16; o > 0; o >>= 1) ssum += __shfl_xor_sync(0xffffffffu, ssum, o);
    float mu = ssum * (1.f / 64.f);
    float dx = vx - mu, dy = vy - mu;
    float sq = dx * dx + dy * dy;
#pragma unroll
    for (int o = 16; o > 0; o >>= 1) sq += __shfl_xor_sync(0xffffffffu, sq, o);
    float inv = rsqrtf(sq * (1.f / 64.f) + 1e-5f);

    float2 gv = ((const float2*)lng)[lane];
    float2 b2 = ((const float2*)lnb)[lane];
    float2 o;
    o.x = dx * inv * gv.x + b2.x;
    o.y = dy * inv * gv.y + b2.y;
    ((float2*)(out + (size_t)n * HID))[lane] = o;
}

// ---------------- launch ----------------
extern "C" void kernel_launch(void* const* d_in, const int* in_sizes, int n_in,
                              void* d_out, int out_size) {
    const float* x    = (const float*)d_in[0];
    const int*   ei   = (const int*)d_in[1];
    const float* W1l  = (const float*)d_in[2];
    const float* W1r  = (const float*)d_in[3];
    const float* att1 = (const float*)d_in[4];
    const float* b1   = (const float*)d_in[5];
    const float* ln1g = (const float*)d_in[6];
    const float* ln1b = (const float*)d_in[7];
    const float* W2l  = (const float*)d_in[8];
    const float* W2r  = (const float*)d_in[9];
    const float* att2 = (const float*)d_in[10];
    const float* b2   = (const float*)d_in[11];
    const float* ln2g = (const float*)d_in[12];
    const float* ln2b = (const float*)d_in[13];
    float* out = (float*)d_out;

    const int* srcp = ei;
    const int* dstp = ei + Ein;

    const int T = 256;

    // fork: CSR build on side stream, concurrent with conv + gemm1
    cudaStream_t s2;
    cudaStreamCreateWithFlags(&s2, cudaStreamNonBlocking);
    cudaEvent_t evF, evJ;
    cudaEventCreateWithFlags(&evF, cudaEventDisableTiming);
    cudaEventCreateWithFlags(&evJ, cudaEventDisableTiming);
    cudaEventRecord(evF, 0);
    cudaStreamWaitEvent(s2, evF, 0);

    k_zero<<<(Nn + T - 1) / T, T, 0, s2>>>();
    k_hist<<<(ET + T - 1) / T, T, 0, s2>>>(dstp);
    k_scan<<<1, 1024, 0, s2>>>();
    k_fill<<<(ET + T - 1) / T, T, 0, s2>>>(srcp, dstp);
    cudaEventRecord(evJ, s2);

    // main stream: conversions + layer1 GEMM
    k_convw<<<(NT * FIN + T - 1) / T, T>>>(W1l, W1r);
    k_convx<<<(Nn * FIN + T - 1) / T, T>>>(x);
    k_convw2<<<(128 * 64 + T - 1) / T, T>>>(W2l, W2r);

    size_t smbytes = SM_ELEMS * sizeof(__half);   // 55296
    cudaFuncSetAttribute(k_gemm1, cudaFuncAttributeMaxDynamicSharedMemorySize, (int)smbytes);
    cudaFuncSetAttribute(k_gemm2, cudaFuncAttributeMaxDynamicSharedMemorySize, (int)smbytes);
    dim3 gg(NT / 128, (Nn + 127) / 128);
    k_gemm1<<<gg, 256, smbytes>>>();

    // join CSR before the gather phase
    cudaStreamWaitEvent(0, evJ, 0);

    // layer1 fused attention + LN + relu -> g_hh (fp16)
    k_gat1<<<(Nn * 32 + T - 1) / T, T>>>(att1, b1, ln1g, ln1b);

    // layer2 GEMM: [50000,64] @ [64,128] fp16 mma 2-term
    k_gemm2<<<(Nn + 127) / 128, 256, smbytes>>>();

    // layer2 fused attention + LN -> out
    k_gat2<<<(Nn * 32 + T - 1) / T, T>>>(att2, b2, ln2g, ln2b, out);
}